// round 10
// baseline (speedup 1.0000x reference)
#include <cuda_runtime.h>
#include <math.h>

// ---------------- problem constants ----------------
#define BB 256
#define NN 32
#define HH 256
#define FF 7
#define TT 496
#define RR 8                 // batch rows per 4-CTA cluster
#define NCLUST (BB / RR)     // 32 clusters
#define NCTA (NCLUST * 4)    // 128 CTAs
#define NT 1024
#define KQN 32               // k per octant (8-way K split, gemm)
#define EPSF 1.1920929e-07f

typedef unsigned long long ull;

// ---------------- device scratch ----------------
// gate-interleaved layouts: local col index lc = hcol*4 + gate
__device__ float g_Wc4[4 * HH * 256];    // node combined weights [q][k][lc]
__device__ float g_Wgi4[4 * HH * 256];   // graph Wih [q][k][lc], gate3 = 0
__device__ float g_Wgh4[4 * HH * 256];   // graph Whh [q][k][lc], gate3 = 0
__device__ float g_bv4[4 * 256];         // node combined bias
__device__ float g_bgi4[4 * 256];        // graph ih bias (gate3 = 0)
__device__ float g_bgh4[4 * 256];        // graph hh bias (gate3 = 0)
__device__ float g_PQi4[4 * FF * 256];   // one-hot(i) gathers (gate3 = 0)
__device__ float g_PQj4[4 * FF * 256];
__device__ float g_Ws1T[HH * 64];        // Ws1 transposed [k][u]
__device__ int   g_idx[BB * NN];
__device__ int   g_rd[TT];
__device__ int   g_cd[TT];

// output layout (float32): [x 57344][adj 262144][batch 8192]
#define OUT_X 0
#define OUT_ADJ 57344
#define OUT_BATCH 319488

// ==================== prep kernel ====================
__global__ void prep_kernel(
    const float* __restrict__ nf,
    const float* __restrict__ Wih_n, const float* __restrict__ Whh_n,
    const float* __restrict__ bih_n, const float* __restrict__ bhh_n,
    const float* __restrict__ Wih_g, const float* __restrict__ Whh_g,
    const float* __restrict__ bih_g, const float* __restrict__ bhh_g,
    const float* __restrict__ Ws1,
    float* __restrict__ out)
{
    long t = (long)blockIdx.x * blockDim.x + threadIdx.x;

    if (t < 262144) {   // g_Wc4: [q][k][col*4+g]
        int q = (int)(t >> 16), k = (int)((t >> 8) & 255), lc = (int)(t & 255);
        int g = lc & 3, col = lc >> 2, hc = q * 64 + col;
        float v;
        if (g == 0)      v = Wih_n[hc * 270 + 14 + k] + Whh_n[hc * 256 + k];
        else if (g == 1) v = Wih_n[(256 + hc) * 270 + 14 + k] + Whh_n[(256 + hc) * 256 + k];
        else if (g == 2) v = Wih_n[(512 + hc) * 270 + 14 + k];
        else             v = Whh_n[(512 + hc) * 256 + k];
        g_Wc4[t] = v; return;
    }
    t -= 262144;
    if (t < 262144) {   // g_Wgi4
        int q = (int)(t >> 16), k = (int)((t >> 8) & 255), lc = (int)(t & 255);
        int g = lc & 3, col = lc >> 2, hc = q * 64 + col;
        g_Wgi4[t] = (g < 3) ? Wih_g[(g * 256 + hc) * 256 + k] : 0.f; return;
    }
    t -= 262144;
    if (t < 262144) {   // g_Wgh4
        int q = (int)(t >> 16), k = (int)((t >> 8) & 255), lc = (int)(t & 255);
        int g = lc & 3, col = lc >> 2, hc = q * 64 + col;
        g_Wgh4[t] = (g < 3) ? Whh_g[(g * 256 + hc) * 256 + k] : 0.f; return;
    }
    t -= 262144;
    if (t < 1024) {     // g_bv4
        int q = (int)(t >> 8), lc = (int)(t & 255);
        int g = lc & 3, col = lc >> 2, hc = q * 64 + col;
        float v;
        if (g == 0)      v = bih_n[hc] + bhh_n[hc];
        else if (g == 1) v = bih_n[256 + hc] + bhh_n[256 + hc];
        else if (g == 2) v = bih_n[512 + hc];
        else             v = bhh_n[512 + hc];
        g_bv4[t] = v; return;
    }
    t -= 1024;
    if (t < 1024) {     // g_bgi4
        int q = (int)(t >> 8), lc = (int)(t & 255);
        int g = lc & 3, col = lc >> 2, hc = q * 64 + col;
        g_bgi4[t] = (g < 3) ? bih_g[g * 256 + hc] : 0.f; return;
    }
    t -= 1024;
    if (t < 1024) {     // g_bgh4
        int q = (int)(t >> 8), lc = (int)(t & 255);
        int g = lc & 3, col = lc >> 2, hc = q * 64 + col;
        g_bgh4[t] = (g < 3) ? bhh_g[g * 256 + hc] : 0.f; return;
    }
    t -= 1024;
    if (t < 7168) {     // g_PQi4: [q][f][lc]
        int q = (int)(t / 1792), rem = (int)(t % 1792);
        int f = rem >> 8, lc = rem & 255;
        int g = lc & 3, col = lc >> 2, hc = q * 64 + col;
        g_PQi4[t] = (g < 3) ? Wih_n[(g * 256 + hc) * 270 + f] : 0.f; return;
    }
    t -= 7168;
    if (t < 7168) {     // g_PQj4
        int q = (int)(t / 1792), rem = (int)(t % 1792);
        int f = rem >> 8, lc = rem & 255;
        int g = lc & 3, col = lc >> 2, hc = q * 64 + col;
        g_PQj4[t] = (g < 3) ? Wih_n[(g * 256 + hc) * 270 + 7 + f] : 0.f; return;
    }
    t -= 7168;
    if (t < 16384) {    // W1T [k][u]
        int k = (int)(t >> 6), u = (int)(t & 63);
        g_Ws1T[t] = Ws1[u * 256 + k]; return;
    }
    t -= 16384;
    if (t < BB * NN) {  // argmax one-hot
        const float* p = nf + t * FF;
        int best = 0;
        #pragma unroll
        for (int f = 0; f < FF; f++) if (p[f] > 0.5f) best = f;
        g_idx[t] = best; return;
    }
    t -= BB * NN;
    if (t < TT) {       // anti-diagonal placement
        int m = (int)t;
        int d = (int)((1.0 + sqrt(1.0 + 8.0 * (double)m)) * 0.5);
        while (d * (d - 1) / 2 > m) d--;
        while ((d + 1) * d / 2 <= m) d++;
        int rr = m - d * (d - 1) / 2;
        g_rd[m] = rr; g_cd[m] = rr + NN - d; return;
    }
    t -= TT;
    if (t < BB * NN * FF) { out[OUT_X + t] = nf[t]; return; }
    t -= BB * NN * FF;
    if (t < BB * NN * NN) { out[OUT_ADJ + t] = 0.f; return; }
    t -= BB * NN * NN;
    if (t < BB * NN) { out[OUT_BATCH + t] = (float)(t >> 5); return; }
}

// ==================== helpers ====================
__device__ __forceinline__ float sigm(float x) { return 1.f / (1.f + expf(-x)); }

__device__ __forceinline__ void ffma2(ull& d, ull a, ull b) {
    asm("fma.rn.f32x2 %0, %1, %2, %0;" : "+l"(d) : "l"(a), "l"(b));
}
__device__ __forceinline__ void fadd2(ull& d, ull a) {
    asm("add.rn.f32x2 %0, %0, %1;" : "+l"(d) : "l"(a));
}
__device__ __forceinline__ ull dup2(float w) {
    ull r;
    asm("mov.b64 %0, {%1, %1};" : "=l"(r) : "r"(__float_as_uint(w)));
    return r;
}
__device__ __forceinline__ float2 unpk(ull v) {
    float2 r;
    r.x = __uint_as_float((unsigned)(v & 0xffffffffu));
    r.y = __uint_as_float((unsigned)(v >> 32));
    return r;
}
__device__ __forceinline__ void st_peer64(float* p, unsigned peer, ull bits) {
    unsigned la = (unsigned)__cvta_generic_to_shared(p);
    unsigned ra;
    asm volatile("mapa.shared::cluster.u32 %0, %1, %2;" : "=r"(ra) : "r"(la), "r"(peer));
    asm volatile("st.shared::cluster.b64 [%0], %1;" :: "r"(ra), "l"(bits) : "memory");
}
#define CLUSTER_SYNC() do { \
    asm volatile("barrier.cluster.arrive.aligned;" ::: "memory"); \
    asm volatile("barrier.cluster.wait.aligned;" ::: "memory"); } while (0)

// ---- gemm: thread owns gate-pair (2 cols) of one h-col, 32 k, 8 rows ----
// acc[g*4+p] = f32x2 rows (2p,2p+1), local gate g in {0,1}
__device__ __forceinline__ void gbody2(const float2 w, const float* __restrict__ hk,
                                       ull acc[8])
{
    ulonglong2 h01 = *(const ulonglong2*)(hk);
    ulonglong2 h23 = *(const ulonglong2*)(hk + 4);
    ull wd = dup2(w.x);
    ffma2(acc[0], wd, h01.x); ffma2(acc[1], wd, h01.y);
    ffma2(acc[2], wd, h23.x); ffma2(acc[3], wd, h23.y);
    wd = dup2(w.y);
    ffma2(acc[4], wd, h01.x); ffma2(acc[5], wd, h01.y);
    ffma2(acc[6], wd, h23.x); ffma2(acc[7], wd, h23.y);
}

// streamed gemm over 32 k-rows, weight float2 from global (stride 256 floats/k)
__device__ __forceinline__ void gemm32(const float* __restrict__ Wp,
                                       const float* __restrict__ hq, ull acc[8])
{
    float2 wb[4];
    #pragma unroll
    for (int x = 0; x < 4; x++) wb[x] = *(const float2*)(Wp + x * 256);
    #pragma unroll
    for (int blk = 0; blk < KQN / 4; blk++) {
        float2 wc[4];
        #pragma unroll
        for (int x = 0; x < 4; x++) wc[x] = wb[x];
        if (blk + 1 < KQN / 4) {
            const float* np = Wp + (blk + 1) * 4 * 256;
            #pragma unroll
            for (int x = 0; x < 4; x++) wb[x] = *(const float2*)(np + x * 256);
        }
        const float* hkb = hq + blk * 4 * 8;
        #pragma unroll
        for (int x = 0; x < 4; x++) gbody2(wc[x], hkb + x * 8, acc);
    }
}

// ---------------- smem layout (float offsets) ----------------
#define SO_W1T  0                          // 16384
#define SO_HA   (SO_W1T + 16384)           // 16384
#define SO_HB   (SO_HA + 2048)             // 18432
#define SO_GA   (SO_HB + 2048)             // 20480
#define SO_GB   (SO_GA + 2048)             // 22528
#define SO_RED  (SO_GB + 2048)             // 24576  64 slots x 256 floats
#define SO_PQI  (SO_RED + 16384)           // 40960
#define SO_PQJ  (SO_PQI + 1792)            // 42752
#define SO_SPS  (SO_PQJ + 1792)            // 44544  16 kq x 64 u x f32x2
#define SO_SVI  (SO_SPS + 2048)            // 46592  128 x 8 ull
#define SO_SBV  (SO_SVI + 2048)            // 48640
#define SO_SBGI (SO_SBV + 256)             // 48896
#define SO_SBGH (SO_SBGI + 256)            // 49152
#define SO_SP4  (SO_SBGH + 256)            // 49408  2 ull
#define SO_IDX  (SO_SP4 + 4)               // 49412  256 ints
#define SMEM_FLOATS (SO_IDX + 256)         // 49668
#define SMEM_BYTES (SMEM_FLOATS * 4)       // 198672

// ==================== main chain kernel ====================
__global__ void __launch_bounds__(NT, 1) __cluster_dims__(4, 1, 1)
chain_kernel(const float* __restrict__ z, const float* __restrict__ uin,
             const float* __restrict__ bs1, const float* __restrict__ Ws2,
             const float* __restrict__ bs2, float* __restrict__ out)
{
    extern __shared__ float sm[];
    float* sW1T = sm + SO_W1T;
    float* hBuf[2] = { sm + SO_HA, sm + SO_HB };
    float* gBuf[2] = { sm + SO_GA, sm + SO_GB };
    float* sred = sm + SO_RED;
    float* sPQi = sm + SO_PQI;
    float* sPQj = sm + SO_PQJ;
    ull*   sps  = (ull*)(sm + SO_SPS);
    ull*   sVI  = (ull*)(sm + SO_SVI);
    float* sbv  = sm + SO_SBV;
    float* sbgi = sm + SO_SBGI;
    float* sbgh = sm + SO_SBGH;
    ull*   sp4  = (ull*)(sm + SO_SP4);
    int*   sidx = (int*)(sm + SO_IDX);

    const int t = threadIdx.x;
    const int q = blockIdx.x & 3;
    const int cid = blockIdx.x >> 2;
    const int b0 = cid * RR;

    const float* WcG  = g_Wc4  + q * 65536;
    const float* WgiG = g_Wgi4 + q * 65536;
    const float* WghG = g_Wgh4 + q * 65536;

    // ---- init smem ----
    for (int x = t; x < 16384; x += NT) sW1T[x] = g_Ws1T[x];
    for (int x = t; x < FF * 256; x += NT) {
        sPQi[x] = g_PQi4[q * FF * 256 + x];
        sPQj[x] = g_PQj4[q * FF * 256 + x];
    }
    for (int x = t; x < 2048; x += NT) {      // graph h init [k][8]
        int k = x >> 3, r = x & 7;
        gBuf[0][x] = z[(b0 + r) * HH + k];
    }
    for (int x = t; x < 256; x += NT) { }     // (no-op, NT>256)
    if (t < 256) {
        sbv[t]  = g_bv4[q * 256 + t];
        sbgi[t] = g_bgi4[q * 256 + t];
        sbgh[t] = g_bgh4[q * 256 + t];
        sidx[t] = g_idx[b0 * NN + t];
    }

    // gemm role: gate-pair of one col, one octant
    const int ch  = t & 127;
    const int col = ch >> 1;
    const int gp  = ch & 1;
    const int oct = t >> 7;
    const float* WcT  = WcG  + col * 4 + gp * 2;
    const float* WgiT = WgiG + col * 4 + gp * 2;
    const float* WghT = WghG + col * 4 + gp * 2;
    // reduce role (t < 128)
    const int rcol = t & 63;
    const int ph   = (t >> 6) & 1;
    const int hcr  = q * 64 + rcol;
    // score role
    const int su  = t & 63;
    const int skq = t >> 6;                  // 0..15
    const float b1r  = bs1[su];
    const float w2r  = Ws2[su];
    const float bs2v = *bs2;
    __syncthreads();
    CLUSTER_SYNC();

    int pb = 0, gpb = 0;

    for (int i = 0; i < NN - 1; i++) {
        pb = 0;
        {   // node_h := graph_h
            const float* gs = gBuf[gpb];
            float* d = hBuf[0];
            for (int x = t; x < 2048; x += NT) d[x] = gs[x];
        }
        __syncthreads();

        for (int j = i + 1; j < NN; j++) {
            float* hR = hBuf[pb];
            float* hW = hBuf[pb ^ 1];

            // ---- node gemm: octant oct ----
            ull acc[8];
            #pragma unroll
            for (int x = 0; x < 8; x++) acc[x] = 0ull;
            gemm32(WcT + oct * KQN * 256, hR + oct * KQN * 8, acc);

            // stage: slot = oct*8 + gate_global*2 + pp
            #pragma unroll
            for (int g = 0; g < 2; g++) {
                int gg = gp * 2 + g;
                #pragma unroll
                for (int pp = 0; pp < 2; pp++) {
                    *(ulonglong2*)(sred + ((oct * 8 + gg * 2 + pp) * 256 + col * 4)) =
                        make_ulonglong2(acc[g * 4 + 2 * pp], acc[g * 4 + 2 * pp + 1]);
                }
            }
            __syncthreads();

            // ---- reduce + in-register GRU activation (t < 128) ----
            if (t < 128) {
                ull s0[4], s1[4];
                #pragma unroll
                for (int g = 0; g < 4; g++) {
                    s0[g] = 0ull; s1[g] = 0ull;
                    #pragma unroll
                    for (int o = 0; o < 8; o++) {
                        ulonglong2 v = *(const ulonglong2*)
                            (sred + ((o * 8 + g * 2 + ph) * 256 + rcol * 4));
                        fadd2(s0[g], v.x); fadd2(s1[g], v.y);
                    }
                }
                float4 bv4 = *(const float4*)(sbv + rcol * 4);
                float bva[4] = { bv4.x, bv4.y, bv4.z, bv4.w };
                float vg[4][4];
                #pragma unroll
                for (int g = 0; g < 4; g++) {
                    float2 a = unpk(s0[g]), b = unpk(s1[g]);
                    vg[g][0] = a.x + bva[g]; vg[g][1] = a.y + bva[g];
                    vg[g][2] = b.x + bva[g]; vg[g][3] = b.y + bva[g];
                }
                #pragma unroll
                for (int r = 0; r < 4; r++) {
                    int rb = ph * 4 + r;
                    int fi = sidx[rb * NN + i];
                    int fj = sidx[rb * NN + j];
                    float4 pi = *(const float4*)(sPQi + fi * 256 + rcol * 4);
                    float4 pj = *(const float4*)(sPQj + fj * 256 + rcol * 4);
                    vg[0][r] += pi.x + pj.x;
                    vg[1][r] += pi.y + pj.y;
                    vg[2][r] += pi.z + pj.z;
                }
                float4 ho4 = *(const float4*)(hR + hcr * 8 + ph * 4);
                float ho[4] = { ho4.x, ho4.y, ho4.z, ho4.w };
                float hn[4];
                #pragma unroll
                for (int r = 0; r < 4; r++) {
                    float gr = sigm(vg[0][r]);
                    float gz = sigm(vg[1][r]);
                    float gn = tanhf(vg[2][r] + gr * vg[3][r]);
                    hn[r] = (1.f - gz) * gn + gz * ho[r];
                }
                ull lo = ((ull)__float_as_uint(hn[1]) << 32) | (ull)__float_as_uint(hn[0]);
                ull hi = ((ull)__float_as_uint(hn[3]) << 32) | (ull)__float_as_uint(hn[2]);
                float* dp = hW + hcr * 8 + ph * 4;
                ((ull*)dp)[0] = lo; ((ull*)dp)[1] = hi;
                #pragma unroll
                for (int pr = 0; pr < 4; pr++) {
                    if (pr != q) {
                        st_peer64(dp, (unsigned)pr, lo);
                        st_peer64(dp + 2, (unsigned)pr, hi);
                    }
                }
            }
            CLUSTER_SYNC();

            // ---- f32x2 score head over CTA's row-pair (rows 2q, 2q+1) ----
            {
                ull sa = 0ull;
                const float* wp = sW1T + skq * 16 * 64 + su;
                const float* hp = hW + skq * 16 * 8 + 2 * q;
                #pragma unroll
                for (int k = 0; k < 16; k++) {
                    ull hpair = *(const ull*)(hp + k * 8);
                    ffma2(sa, dup2(wp[k * 64]), hpair);
                }
                sps[skq * 64 + su] = sa;
            }
            __syncthreads();
            if (t < 64) {
                ull sum = 0ull;
                #pragma unroll
                for (int x = 0; x < 16; x++) fadd2(sum, sps[x * 64 + t]);
                float2 s = unpk(sum);
                float hx = fmaxf(s.x + b1r, 0.f) * w2r;
                float hy = fmaxf(s.y + b1r, 0.f) * w2r;
                ull sc = ((ull)__float_as_uint(hy) << 32) | (ull)__float_as_uint(hx);
                #pragma unroll
                for (int o = 16; o; o >>= 1) {
                    ull other = __shfl_down_sync(0xffffffffu, sc, o);
                    fadd2(sc, other);
                }
                if ((t & 31) == 0) sp4[t >> 5] = sc;
                asm volatile("bar.sync 2, 64;" ::: "memory");
                if (t < 2) {
                    ull tot = sp4[0];
                    fadd2(tot, sp4[1]);
                    float2 v = unpk(tot);
                    float val = t ? v.y : v.x;
                    float prob = sigm(val + bs2v);
                    int m = i * (NN - 1) - (i * (i - 1)) / 2 + (j - i - 1);
                    int b = b0 + 2 * q + t;
                    float uu = uin[b * TT + m];
                    float pc = fminf(fmaxf(prob, EPSF), 1.f - EPSF);
                    float e;
                    if (pc < 0.499f || pc > 0.501f) {
                        e = (log1pf(-pc + uu * (2.f * pc - 1.f)) - log1pf(-pc))
                          / (logf(pc) - log1pf(-pc));
                    } else {
                        e = uu;
                    }
                    int rr = g_rd[m], cc = g_cd[m];
                    float* adj = out + OUT_ADJ + b * (NN * NN);
                    adj[rr * NN + cc] = e;
                    adj[cc * NN + rr] = e;
                }
            }
            pb ^= 1;
        }

        // ---- graph GRU: two passes sharing the staging region ----
        if (i < NN - 2) {
            const float* hfin = hBuf[pb];
            const float* ghR = gBuf[gpb];
            float* ghW = gBuf[gpb ^ 1];

            // pass 1: gi = Wgi @ hfin
            {
                ull acc[8];
                #pragma unroll
                for (int x = 0; x < 8; x++) acc[x] = 0ull;
                gemm32(WgiT + oct * KQN * 256, hfin + oct * KQN * 8, acc);
                #pragma unroll
                for (int g = 0; g < 2; g++) {
                    int gg = gp * 2 + g;
                    #pragma unroll
                    for (int pp = 0; pp < 2; pp++) {
                        *(ulonglong2*)(sred + ((oct * 8 + gg * 2 + pp) * 256 + col * 4)) =
                            make_ulonglong2(acc[g * 4 + 2 * pp], acc[g * 4 + 2 * pp + 1]);
                    }
                }
            }
            __syncthreads();
            if (t < 128) {
                #pragma unroll
                for (int g = 0; g < 4; g++) {
                    ull s0 = 0ull, s1 = 0ull;
                    #pragma unroll
                    for (int o = 0; o < 8; o++) {
                        ulonglong2 v = *(const ulonglong2*)
                            (sred + ((o * 8 + g * 2 + ph) * 256 + rcol * 4));
                        fadd2(s0, v.x); fadd2(s1, v.y);
                    }
                    sVI[t * 8 + g * 2] = s0;
                    sVI[t * 8 + g * 2 + 1] = s1;
                }
            }
            __syncthreads();

            // pass 2: gh = Wgh @ ghR
            {
                ull acc[8];
                #pragma unroll
                for (int x = 0; x < 8; x++) acc[x] = 0ull;
                gemm32(WghT + oct * KQN * 256, ghR + oct * KQN * 8, acc);
                #pragma unroll
                for (int g = 0; g < 2; g++) {
                    int gg = gp * 2 + g;
                    #pragma unroll
                    for (int pp = 0; pp < 2; pp++) {
                        *(ulonglong2*)(sred + ((oct * 8 + gg * 2 + pp) * 256 + col * 4)) =
                            make_ulonglong2(acc[g * 4 + 2 * pp], acc[g * 4 + 2 * pp + 1]);
                    }
                }
            }
            __syncthreads();
            if (t < 128) {
                float vi[3][4], vh[3][4];
                float4 bgi4 = *(const float4*)(sbgi + rcol * 4);
                float4 bgh4 = *(const float4*)(sbgh + rcol * 4);
                float bgia[3] = { bgi4.x, bgi4.y, bgi4.z };
                float bgha[3] = { bgh4.x, bgh4.y, bgh4.z };
                #pragma unroll
                for (int g = 0; g < 3; g++) {
                    float2 a = unpk(sVI[t * 8 + g * 2]);
                    float2 b = unpk(sVI[t * 8 + g * 2 + 1]);
                    vi[g][0] = a.x + bgia[g]; vi[g][1] = a.y + bgia[g];
                    vi[g][2] = b.x + bgia[g]; vi[g][3] = b.y + bgia[g];
                    ull s0 = 0ull, s1 = 0ull;
                    #pragma unroll
                    for (int o = 0; o < 8; o++) {
                        ulonglong2 v = *(const ulonglong2*)
                            (sred + ((o * 8 + g * 2 + ph) * 256 + rcol * 4));
                        fadd2(s0, v.x); fadd2(s1, v.y);
                    }
                    float2 c = unpk(s0), d = unpk(s1);
                    vh[g][0] = c.x + bgha[g]; vh[g][1] = c.y + bgha[g];
                    vh[g][2] = d.x + bgha[g]; vh[g][3] = d.y + bgha[g];
                }
                float4 go4 = *(const float4*)(ghR + hcr * 8 + ph * 4);
                float go[4] = { go4.x, go4.y, go4.z, go4.w };
                float hn[4];
                #pragma unroll
                for (int r = 0; r < 4; r++) {
                    float rr = sigm(vi[0][r] + vh[0][r]);
                    float zz = sigm(vi[1][r] + vh[1][r]);
                    float nn = tanhf(vi[2][r] + rr * vh[2][r]);
                    hn[r] = (1.f - zz) * nn + zz * go[r];
                }
                ull lo = ((ull)__float_as_uint(hn[1]) << 32) | (ull)__float_as_uint(hn[0]);
                ull hi = ((ull)__float_as_uint(hn[3]) << 32) | (ull)__float_as_uint(hn[2]);
                float* dp = ghW + hcr * 8 + ph * 4;
                ((ull*)dp)[0] = lo; ((ull*)dp)[1] = hi;
                #pragma unroll
                for (int pr = 0; pr < 4; pr++) {
                    if (pr != q) {
                        st_peer64(dp, (unsigned)pr, lo);
                        st_peer64(dp + 2, (unsigned)pr, hi);
                    }
                }
            }
            CLUSTER_SYNC();
            gpb ^= 1;
        }
    }
}

// ==================== launch ====================
extern "C" void kernel_launch(void* const* d_in, const int* in_sizes, int n_in,
                              void* d_out, int out_size)
{
    const float* z     = (const float*)d_in[0];
    const float* nf    = (const float*)d_in[1];
    const float* u     = (const float*)d_in[2];
    const float* Wih_n = (const float*)d_in[3];
    const float* Whh_n = (const float*)d_in[4];
    const float* bih_n = (const float*)d_in[5];
    const float* bhh_n = (const float*)d_in[6];
    const float* Wih_g = (const float*)d_in[7];
    const float* Whh_g = (const float*)d_in[8];
    const float* bih_g = (const float*)d_in[9];
    const float* bhh_g = (const float*)d_in[10];
    const float* Ws1   = (const float*)d_in[11];
    const float* bs1   = (const float*)d_in[12];
    const float* Ws2   = (const float*)d_in[13];
    const float* bs2   = (const float*)d_in[14];
    float* out = (float*)d_out;

    const long total = 262144L * 3 + 1024 * 3 + 7168 * 2 + 16384
                     + BB * NN + TT + BB * NN * FF + BB * NN * NN + BB * NN;
    int blocks = (int)((total + 255) / 256);
    prep_kernel<<<blocks, 256>>>(nf, Wih_n, Whh_n, bih_n, bhh_n,
                                 Wih_g, Whh_g, bih_g, bhh_g, Ws1, out);

    cudaFuncSetAttribute(chain_kernel,
                         cudaFuncAttributeMaxDynamicSharedMemorySize, SMEM_BYTES);
    chain_kernel<<<NCTA, NT, SMEM_BYTES>>>(z, u, bs1, Ws2, bs2, out);
}

// round 11
// speedup vs baseline: 1.3348x; 1.3348x over previous
#include <cuda_runtime.h>
#include <math.h>

// ---------------- problem constants ----------------
#define BB 256
#define NN 32
#define HH 256
#define FF 7
#define TT 496
#define RR 8                 // batch rows per 4-CTA cluster
#define NCLUST (BB / RR)     // 32 clusters
#define NCTA (NCLUST * 4)    // 128 CTAs
#define NT 512
#define KQN 32               // k per octant (8-way K split, node gemm)
#define KQG 64               // k per quarter (graph gemm)
#define EPSF 1.1920929e-07f

typedef unsigned long long ull;

// ---------------- device scratch ----------------
// gate-interleaved layouts: local col index lc = hcol*4 + gate
__device__ float g_Wc4[4 * HH * 256];    // node combined weights [q][k][lc]
__device__ float g_Wgi4[4 * HH * 256];   // graph Wih [q][k][lc], gate3 = 0
__device__ float g_Wgh4[4 * HH * 256];   // graph Whh [q][k][lc], gate3 = 0
__device__ float g_bv4[4 * 256];         // node combined bias
__device__ float g_bgi4[4 * 256];        // graph ih bias (gate3 = 0)
__device__ float g_bgh4[4 * 256];        // graph hh bias (gate3 = 0)
__device__ float g_PQi4[4 * FF * 256];   // one-hot(i) gathers (gate3 = 0)
__device__ float g_PQj4[4 * FF * 256];
__device__ float g_Ws1T[HH * 64];        // Ws1 transposed [k][u]
__device__ int   g_idx[BB * NN];
__device__ int   g_rd[TT];
__device__ int   g_cd[TT];

// output layout (float32): [x 57344][adj 262144][batch 8192]
#define OUT_X 0
#define OUT_ADJ 57344
#define OUT_BATCH 319488

// ==================== prep kernel (same as R8) ====================
__global__ void prep_kernel(
    const float* __restrict__ nf,
    const float* __restrict__ Wih_n, const float* __restrict__ Whh_n,
    const float* __restrict__ bih_n, const float* __restrict__ bhh_n,
    const float* __restrict__ Wih_g, const float* __restrict__ Whh_g,
    const float* __restrict__ bih_g, const float* __restrict__ bhh_g,
    const float* __restrict__ Ws1,
    float* __restrict__ out)
{
    long t = (long)blockIdx.x * blockDim.x + threadIdx.x;

    if (t < 262144) {   // g_Wc4: [q][k][col*4+g]
        int q = (int)(t >> 16), k = (int)((t >> 8) & 255), lc = (int)(t & 255);
        int g = lc & 3, col = lc >> 2, hc = q * 64 + col;
        float v;
        if (g == 0)      v = Wih_n[hc * 270 + 14 + k] + Whh_n[hc * 256 + k];
        else if (g == 1) v = Wih_n[(256 + hc) * 270 + 14 + k] + Whh_n[(256 + hc) * 256 + k];
        else if (g == 2) v = Wih_n[(512 + hc) * 270 + 14 + k];
        else             v = Whh_n[(512 + hc) * 256 + k];
        g_Wc4[t] = v; return;
    }
    t -= 262144;
    if (t < 262144) {   // g_Wgi4
        int q = (int)(t >> 16), k = (int)((t >> 8) & 255), lc = (int)(t & 255);
        int g = lc & 3, col = lc >> 2, hc = q * 64 + col;
        g_Wgi4[t] = (g < 3) ? Wih_g[(g * 256 + hc) * 256 + k] : 0.f; return;
    }
    t -= 262144;
    if (t < 262144) {   // g_Wgh4
        int q = (int)(t >> 16), k = (int)((t >> 8) & 255), lc = (int)(t & 255);
        int g = lc & 3, col = lc >> 2, hc = q * 64 + col;
        g_Wgh4[t] = (g < 3) ? Whh_g[(g * 256 + hc) * 256 + k] : 0.f; return;
    }
    t -= 262144;
    if (t < 1024) {     // g_bv4
        int q = (int)(t >> 8), lc = (int)(t & 255);
        int g = lc & 3, col = lc >> 2, hc = q * 64 + col;
        float v;
        if (g == 0)      v = bih_n[hc] + bhh_n[hc];
        else if (g == 1) v = bih_n[256 + hc] + bhh_n[256 + hc];
        else if (g == 2) v = bih_n[512 + hc];
        else             v = bhh_n[512 + hc];
        g_bv4[t] = v; return;
    }
    t -= 1024;
    if (t < 1024) {     // g_bgi4
        int q = (int)(t >> 8), lc = (int)(t & 255);
        int g = lc & 3, col = lc >> 2, hc = q * 64 + col;
        g_bgi4[t] = (g < 3) ? bih_g[g * 256 + hc] : 0.f; return;
    }
    t -= 1024;
    if (t < 1024) {     // g_bgh4
        int q = (int)(t >> 8), lc = (int)(t & 255);
        int g = lc & 3, col = lc >> 2, hc = q * 64 + col;
        g_bgh4[t] = (g < 3) ? bhh_g[g * 256 + hc] : 0.f; return;
    }
    t -= 1024;
    if (t < 7168) {     // g_PQi4: [q][f][lc]
        int q = (int)(t / 1792), rem = (int)(t % 1792);
        int f = rem >> 8, lc = rem & 255;
        int g = lc & 3, col = lc >> 2, hc = q * 64 + col;
        g_PQi4[t] = (g < 3) ? Wih_n[(g * 256 + hc) * 270 + f] : 0.f; return;
    }
    t -= 7168;
    if (t < 7168) {     // g_PQj4
        int q = (int)(t / 1792), rem = (int)(t % 1792);
        int f = rem >> 8, lc = rem & 255;
        int g = lc & 3, col = lc >> 2, hc = q * 64 + col;
        g_PQj4[t] = (g < 3) ? Wih_n[(g * 256 + hc) * 270 + 7 + f] : 0.f; return;
    }
    t -= 7168;
    if (t < 16384) {    // W1T [k][u]
        int k = (int)(t >> 6), u = (int)(t & 63);
        g_Ws1T[t] = Ws1[u * 256 + k]; return;
    }
    t -= 16384;
    if (t < BB * NN) {  // argmax one-hot
        const float* p = nf + t * FF;
        int best = 0;
        #pragma unroll
        for (int f = 0; f < FF; f++) if (p[f] > 0.5f) best = f;
        g_idx[t] = best; return;
    }
    t -= BB * NN;
    if (t < TT) {       // anti-diagonal placement
        int m = (int)t;
        int d = (int)((1.0 + sqrt(1.0 + 8.0 * (double)m)) * 0.5);
        while (d * (d - 1) / 2 > m) d--;
        while ((d + 1) * d / 2 <= m) d++;
        int rr = m - d * (d - 1) / 2;
        g_rd[m] = rr; g_cd[m] = rr + NN - d; return;
    }
    t -= TT;
    if (t < BB * NN * FF) { out[OUT_X + t] = nf[t]; return; }
    t -= BB * NN * FF;
    if (t < BB * NN * NN) { out[OUT_ADJ + t] = 0.f; return; }
    t -= BB * NN * NN;
    if (t < BB * NN) { out[OUT_BATCH + t] = (float)(t >> 5); return; }
}

// ==================== helpers ====================
__device__ __forceinline__ float sigm(float x) { return 1.f / (1.f + expf(-x)); }

__device__ __forceinline__ void ffma2(ull& d, ull a, ull b) {
    asm("fma.rn.f32x2 %0, %1, %2, %0;" : "+l"(d) : "l"(a), "l"(b));
}
__device__ __forceinline__ void fadd2(ull& d, ull a) {
    asm("add.rn.f32x2 %0, %0, %1;" : "+l"(d) : "l"(a));
}
__device__ __forceinline__ ull dup2(float w) {
    ull r;
    asm("mov.b64 %0, {%1, %1};" : "=l"(r) : "r"(__float_as_uint(w)));
    return r;
}
__device__ __forceinline__ float2 unpk(ull v) {
    float2 r;
    r.x = __uint_as_float((unsigned)(v & 0xffffffffu));
    r.y = __uint_as_float((unsigned)(v >> 32));
    return r;
}
__device__ __forceinline__ void st_peer64(float* p, unsigned peer, ull bits) {
    unsigned la = (unsigned)__cvta_generic_to_shared(p);
    unsigned ra;
    asm volatile("mapa.shared::cluster.u32 %0, %1, %2;" : "=r"(ra) : "r"(la), "r"(peer));
    asm volatile("st.shared::cluster.b64 [%0], %1;" :: "r"(ra), "l"(bits) : "memory");
}
__device__ __forceinline__ void st_peer32(unsigned laddr, unsigned peer, float v) {
    unsigned ra;
    asm volatile("mapa.shared::cluster.u32 %0, %1, %2;" : "=r"(ra) : "r"(laddr), "r"(peer));
    asm volatile("st.shared::cluster.b32 [%0], %1;" :: "r"(ra), "r"(__float_as_uint(v)) : "memory");
}
__device__ __forceinline__ void mbar_init(unsigned addr, unsigned cnt) {
    asm volatile("mbarrier.init.shared.b64 [%0], %1;" :: "r"(addr), "r"(cnt) : "memory");
}
__device__ __forceinline__ void mbar_arrive_cluster(unsigned laddr, unsigned rank) {
    unsigned ra;
    asm volatile("mapa.shared::cluster.u32 %0, %1, %2;" : "=r"(ra) : "r"(laddr), "r"(rank));
    asm volatile("mbarrier.arrive.release.cluster.shared::cluster.b64 _, [%0];"
                 :: "r"(ra) : "memory");
}
__device__ __forceinline__ void mbar_wait(unsigned addr, unsigned parity) {
    asm volatile(
        "{\n\t.reg .pred P1;\n\t"
        "WAIT_LOOP_%=:\n\t"
        "mbarrier.try_wait.parity.acquire.cluster.shared::cta.b64 P1, [%0], %1, 0x989680;\n\t"
        "@P1 bra.uni WAIT_DONE_%=;\n\t"
        "bra.uni WAIT_LOOP_%=;\n\t"
        "WAIT_DONE_%=:\n\t}"
        :: "r"(addr), "r"(parity) : "memory");
}
#define CLUSTER_SYNC() do { \
    asm volatile("barrier.cluster.arrive.aligned;" ::: "memory"); \
    asm volatile("barrier.cluster.wait.aligned;" ::: "memory"); } while (0)

// two alternating mbarriers; all 512 threads reach this at the same points
#define EXCHANGE() do { \
    __syncthreads(); \
    unsigned mb_ = mbarB32 + (unsigned)((xstep & 1) * 8); \
    if (t < 4) mbar_arrive_cluster(mb_, (unsigned)t); \
    mbar_wait(mb_, (unsigned)((xstep >> 1) & 1)); \
    xstep++; \
} while (0)

// ---- gemm core: one thread owns 4 gate-cols of one h-col ----
// acc[g*4 + p] = f32x2 over rows (2p, 2p+1), gate g.
__device__ __forceinline__ void gbody(const float4 w, const float* __restrict__ hk,
                                      ull acc[16])
{
    ulonglong2 h01 = *(const ulonglong2*)(hk);
    ulonglong2 h23 = *(const ulonglong2*)(hk + 4);
    ull wd;
    wd = dup2(w.x);
    ffma2(acc[0], wd, h01.x); ffma2(acc[1], wd, h01.y);
    ffma2(acc[2], wd, h23.x); ffma2(acc[3], wd, h23.y);
    wd = dup2(w.y);
    ffma2(acc[4], wd, h01.x); ffma2(acc[5], wd, h01.y);
    ffma2(acc[6], wd, h23.x); ffma2(acc[7], wd, h23.y);
    wd = dup2(w.z);
    ffma2(acc[8],  wd, h01.x); ffma2(acc[9],  wd, h01.y);
    ffma2(acc[10], wd, h23.x); ffma2(acc[11], wd, h23.y);
    wd = dup2(w.w);
    ffma2(acc[12], wd, h01.x); ffma2(acc[13], wd, h01.y);
    ffma2(acc[14], wd, h23.x); ffma2(acc[15], wd, h23.y);
}

// streamed gemm over NK k-rows, weights from global (stride 256 floats/k)
template <int NK>
__device__ __forceinline__ void gemm_glob(const float* __restrict__ Wp,
                                          const float* __restrict__ hq, ull acc[16])
{
    float4 wb[4];
    #pragma unroll
    for (int x = 0; x < 4; x++) wb[x] = *(const float4*)(Wp + x * 256);
    #pragma unroll
    for (int blk = 0; blk < NK / 4; blk++) {
        float4 wc[4];
        #pragma unroll
        for (int x = 0; x < 4; x++) wc[x] = wb[x];
        if (blk + 1 < NK / 4) {
            const float* np = Wp + (blk + 1) * 4 * 256;
            #pragma unroll
            for (int x = 0; x < 4; x++) wb[x] = *(const float4*)(np + x * 256);
        }
        const float* hkb = hq + blk * 4 * 8;
        #pragma unroll
        for (int x = 0; x < 4; x++) gbody(wc[x], hkb + x * 8, acc);
    }
}

// ---------------- smem layout (float offsets) ----------------
#define SO_WC   0                          // 2 octants resident: 2*32*256 = 16384
#define SO_W1L  (SO_WC + 2 * KQN * 256)    // 16384  W1T local slice [c][u] 64x64
#define SO_HA   (SO_W1L + 4096)            // 20480
#define SO_HB   (SO_HA + 2048)             // 22528
#define SO_GA   (SO_HB + 2048)             // 24576
#define SO_GB   (SO_GA + 2048)             // 26624
#define SO_RED  (SO_GB + 2048)             // 28672  64 slots x 256 floats
#define SO_PQI  (SO_RED + 16384)           // 45056
#define SO_PQJ  (SO_PQI + 1792)            // 46848
#define SO_SVI  (SO_PQJ + 1792)            // 48640  graph pass-1 staging (128 x 8 ull)
#define SO_PB   (SO_SVI + 2048)            // 50688  score partials 2 buf x 4 src x 128
#define SO_SP4  (SO_PB + 1024)             // 51712  4 warp partials
#define SO_IDX  (SO_SP4 + 4)               // 51716  256 ints
#define SO_MBAR (SO_IDX + 256)             // 51972  (even -> 8B aligned) 2 mbarriers
#define SMEM_FLOATS (SO_MBAR + 4)          // 51976
#define SMEM_BYTES (SMEM_FLOATS * 4)       // 207904

// ==================== main chain kernel ====================
__global__ void __launch_bounds__(NT, 1) __cluster_dims__(4, 1, 1)
chain_kernel(const float* __restrict__ z, const float* __restrict__ uin,
             const float* __restrict__ bs1, const float* __restrict__ Ws2,
             const float* __restrict__ bs2, float* __restrict__ out)
{
    extern __shared__ float sm[];
    float* sWc  = sm + SO_WC;
    float* sW1L = sm + SO_W1L;
    float* hBuf[2] = { sm + SO_HA, sm + SO_HB };
    float* gBuf[2] = { sm + SO_GA, sm + SO_GB };
    float* sred = sm + SO_RED;
    float* sPQi = sm + SO_PQI;
    float* sPQj = sm + SO_PQJ;
    ull*   sVI  = (ull*)(sm + SO_SVI);
    float* sPB  = sm + SO_PB;
    float* sp4  = sm + SO_SP4;
    int*   sidx = (int*)(sm + SO_IDX);

    const int t = threadIdx.x;
    const int q = blockIdx.x & 3;
    const int cid = blockIdx.x >> 2;
    const int b0 = cid * RR;
    const unsigned sb32 = (unsigned)__cvta_generic_to_shared(sm);
    const unsigned mbarB32 = sb32 + SO_MBAR * 4;

    const float* WcG  = g_Wc4  + q * 65536;
    const float* WgiG = g_Wgi4 + q * 65536;
    const float* WghG = g_Wgh4 + q * 65536;

    // ---- init smem ----
    for (int x = t; x < 2 * KQN * 256; x += NT) sWc[x] = WcG[x];  // octants 0,1 resident
    for (int x = t; x < 4096; x += NT) sW1L[x] = g_Ws1T[q * 4096 + x];
    for (int x = t; x < FF * 256; x += NT) {
        sPQi[x] = g_PQi4[q * FF * 256 + x];
        sPQj[x] = g_PQj4[q * FF * 256 + x];
    }
    for (int x = t; x < 2048; x += NT) {      // graph h init [k][8]
        int k = x >> 3, r = x & 7;
        gBuf[0][x] = z[(b0 + r) * HH + k];
    }
    if (t < 256) sidx[t] = g_idx[b0 * NN + t];
    if (t == 0) {
        mbar_init(mbarB32, 4);
        mbar_init(mbarB32 + 8, 4);
    }

    // gemm role: 4 gate-cols of one h-col, one octant
    const int col = t & 63;
    const int oct = t >> 6;
    // reduce/activation role (t < 128)
    const int ph = oct & 1;                 // row-half: rows 4ph..4ph+3
    const int hc = q * 64 + col;
    // score-partial role (all 512): unit pu, row prow
    const int pu = t & 63;
    const int prow = t >> 6;                // 0..7
    // finalize constants (t < 128)
    const float b1r  = bs1[t & 63];
    const float w2r  = Ws2[t & 63];
    const float bs2v = *bs2;

    // reduce-thread bias constants
    float bva[4]  = {0,0,0,0};
    float bgia[4] = {0,0,0,0};
    float bgha[4] = {0,0,0,0};
    if (t < 128) {
        float4 b;
        b = *(const float4*)(g_bv4  + q * 256 + col * 4);
        bva[0]=b.x; bva[1]=b.y; bva[2]=b.z; bva[3]=b.w;
        b = *(const float4*)(g_bgi4 + q * 256 + col * 4);
        bgia[0]=b.x; bgia[1]=b.y; bgia[2]=b.z; bgia[3]=b.w;
        b = *(const float4*)(g_bgh4 + q * 256 + col * 4);
        bgha[0]=b.x; bgha[1]=b.y; bgha[2]=b.z; bgha[3]=b.w;
    }
    __syncthreads();
    CLUSTER_SYNC();      // mbarrier inits + smem visible cluster-wide

    int pb = 0, gpb = 0;
    int xstep = 0;       // exchange counter (selects barrier + parity)

    for (int i = 0; i < NN - 1; i++) {
        pb = 0;
        {   // node_h := graph_h
            const float* gs = gBuf[gpb];
            float* d = hBuf[0];
            for (int x = t; x < 2048; x += NT) d[x] = gs[x];
        }
        __syncthreads();

        int fiR[4];
        if (t < 128) {
            #pragma unroll
            for (int r = 0; r < 4; r++) fiR[r] = sidx[(ph * 4 + r) * NN + i];
        }

        for (int j = i + 1; j < NN; j++) {
            float* hR = hBuf[pb];
            float* hW = hBuf[pb ^ 1];
            const int pbsel = xstep & 1;     // partial-buffer parity for THIS step

            // ---- node gemm: octant oct (0,1 resident in smem) ----
            ull acc[16];
            #pragma unroll
            for (int x = 0; x < 16; x++) acc[x] = 0ull;
            const float* hq = hR + oct * KQN * 8;
            if (oct <= 1) {
                const float* wp = sWc + oct * KQN * 256 + col * 4;
                #pragma unroll 4
                for (int k = 0; k < KQN; k++)
                    gbody(*(const float4*)(wp + k * 256), hq + k * 8, acc);
            } else {
                gemm_glob<KQN>(WcG + oct * KQN * 256 + col * 4, hq, acc);
            }
            // stage partials: slot = oct*8 + g*2 + pp
            #pragma unroll
            for (int g = 0; g < 4; g++) {
                #pragma unroll
                for (int pp = 0; pp < 2; pp++) {
                    *(ulonglong2*)(sred + ((oct * 8 + g * 2 + pp) * 256 + col * 4)) =
                        make_ulonglong2(acc[g * 4 + 2 * pp], acc[g * 4 + 2 * pp + 1]);
                }
            }
            __syncthreads();

            // ---- reduce + in-register GRU activation (t < 128) ----
            if (t < 128) {
                ull s0[4], s1[4];
                #pragma unroll
                for (int g = 0; g < 4; g++) {
                    s0[g] = 0ull; s1[g] = 0ull;
                    #pragma unroll
                    for (int o = 0; o < 8; o++) {
                        ulonglong2 v = *(const ulonglong2*)
                            (sred + ((o * 8 + g * 2 + ph) * 256 + col * 4));
                        fadd2(s0[g], v.x); fadd2(s1[g], v.y);
                    }
                }
                float vg[4][4];
                #pragma unroll
                for (int g = 0; g < 4; g++) {
                    float2 a = unpk(s0[g]), b = unpk(s1[g]);
                    vg[g][0] = a.x + bva[g]; vg[g][1] = a.y + bva[g];
                    vg[g][2] = b.x + bva[g]; vg[g][3] = b.y + bva[g];
                }
                #pragma unroll
                for (int r = 0; r < 4; r++) {
                    int rb = ph * 4 + r;
                    int fj = sidx[rb * NN + j];
                    float4 pi = *(const float4*)(sPQi + fiR[r] * 256 + col * 4);
                    float4 pj = *(const float4*)(sPQj + fj * 256 + col * 4);
                    vg[0][r] += pi.x + pj.x;
                    vg[1][r] += pi.y + pj.y;
                    vg[2][r] += pi.z + pj.z;
                }
                float4 ho4 = *(const float4*)(hR + hc * 8 + ph * 4);
                float ho[4] = { ho4.x, ho4.y, ho4.z, ho4.w };
                float hn[4];
                #pragma unroll
                for (int r = 0; r < 4; r++) {
                    float gr = sigm(vg[0][r]);
                    float gz = sigm(vg[1][r]);
                    float gn = tanhf(vg[2][r] + gr * vg[3][r]);
                    hn[r] = (1.f - gz) * gn + gz * ho[r];
                }
                ull lo = ((ull)__float_as_uint(hn[1]) << 32) | (ull)__float_as_uint(hn[0]);
                ull hi = ((ull)__float_as_uint(hn[3]) << 32) | (ull)__float_as_uint(hn[2]);
                float* dp = hW + hc * 8 + ph * 4;
                ((ull*)dp)[0] = lo; ((ull*)dp)[1] = hi;
                #pragma unroll
                for (int pr = 0; pr < 4; pr++) {
                    if (pr != q) {
                        st_peer64(dp, (unsigned)pr, lo);
                        st_peer64(dp + 2, (unsigned)pr, hi);
                    }
                }
            }
            __syncthreads();   // local h slice complete

            // ---- local score partials over own 64 cols (overlaps exchange) ----
            {
                float a0 = 0.f, a1 = 0.f;
                const float* wp = sW1L + pu;               // [c][u] stride 64
                const float* hp = hW + (q * 64) * 8 + prow; // [c] stride 8 (broadcast)
                #pragma unroll 8
                for (int c = 0; c < 64; c += 2) {
                    a0 = fmaf(wp[c * 64],       hp[c * 8],       a0);
                    a1 = fmaf(wp[(c + 1) * 64], hp[(c + 1) * 8], a1);
                }
                float pv = a0 + a1;
                int tr = prow >> 1, rl = prow & 1;          // owner CTA, local row
                unsigned laddr = sb32 +
                    (unsigned)((SO_PB + pbsel * 512 + q * 128 + pu * 2 + rl) * 4);
                st_peer32(laddr, (unsigned)tr, pv);
            }
            EXCHANGE();

            // ---- finalize score + edge for own rows 2q, 2q+1 (t < 128) ----
            if (t < 128) {
                int u = t & 63, rl = (t >> 6) & 1;
                const float* pbp = sPB + pbsel * 512;
                float ssum = pbp[u * 2 + rl] + pbp[128 + u * 2 + rl]
                           + pbp[256 + u * 2 + rl] + pbp[384 + u * 2 + rl];
                float hid = fmaxf(ssum + b1r, 0.f) * w2r;
                #pragma unroll
                for (int o = 16; o; o >>= 1)
                    hid += __shfl_down_sync(0xffffffffu, hid, o);
                if ((t & 31) == 0) sp4[t >> 5] = hid;
                asm volatile("bar.sync 1, 128;" ::: "memory");
                if (t < 2) {
                    float s = sp4[2 * t] + sp4[2 * t + 1] + bs2v;
                    float prob = sigm(s);
                    int m = i * (NN - 1) - (i * (i - 1)) / 2 + (j - i - 1);
                    int b = b0 + 2 * q + t;
                    float uu = uin[b * TT + m];
                    float pc = fminf(fmaxf(prob, EPSF), 1.f - EPSF);
                    float e;
                    if (pc < 0.499f || pc > 0.501f) {
                        e = (log1pf(-pc + uu * (2.f * pc - 1.f)) - log1pf(-pc))
                          / (logf(pc) - log1pf(-pc));
                    } else {
                        e = uu;
                    }
                    int rr = g_rd[m], cc = g_cd[m];
                    float* adj = out + OUT_ADJ + b * (NN * NN);
                    adj[rr * NN + cc] = e;
                    adj[cc * NN + rr] = e;
                }
            }
            pb ^= 1;
        }

        // ---- graph GRU: two passes sharing the staging region ----
        if (i < NN - 2) {
            const float* hfin = hBuf[pb];
            const float* ghR = gBuf[gpb];
            float* ghW = gBuf[gpb ^ 1];

            // pass 1: gi = Wgi @ hfin  (octants pair up: 4-way K split per matrix)
            {
                ull acc[16];
                #pragma unroll
                for (int x = 0; x < 16; x++) acc[x] = 0ull;
                if (oct < 4)
                    gemm_glob<KQG>(WgiG + oct * KQG * 256 + col * 4,
                                   hfin + oct * KQG * 8, acc);
                else
                    gemm_glob<KQG>(WghG + (oct - 4) * KQG * 256 + col * 4,
                                   ghR + (oct - 4) * KQG * 8, acc);
                #pragma unroll
                for (int g = 0; g < 4; g++) {
                    #pragma unroll
                    for (int pp = 0; pp < 2; pp++) {
                        *(ulonglong2*)(sred + ((oct * 8 + g * 2 + pp) * 256 + col * 4)) =
                            make_ulonglong2(acc[g * 4 + 2 * pp], acc[g * 4 + 2 * pp + 1]);
                    }
                }
            }
            __syncthreads();

            if (t < 128) {
                float vi[3][4], vh[3][4];
                #pragma unroll
                for (int g = 0; g < 3; g++) {
                    ull i0 = 0ull, i1 = 0ull, h0 = 0ull, h1 = 0ull;
                    #pragma unroll
                    for (int o = 0; o < 4; o++) {
                        ulonglong2 v = *(const ulonglong2*)
                            (sred + ((o * 8 + g * 2 + ph) * 256 + col * 4));
                        fadd2(i0, v.x); fadd2(i1, v.y);
                    }
                    #pragma unroll
                    for (int o = 4; o < 8; o++) {
                        ulonglong2 v = *(const ulonglong2*)
                            (sred + ((o * 8 + g * 2 + ph) * 256 + col * 4));
                        fadd2(h0, v.x); fadd2(h1, v.y);
                    }
                    float2 a = unpk(i0), b = unpk(i1);
                    vi[g][0] = a.x + bgia[g]; vi[g][1] = a.y + bgia[g];
                    vi[g][2] = b.x + bgia[g]; vi[g][3] = b.y + bgia[g];
                    float2 c = unpk(h0), d = unpk(h1);
                    vh[g][0] = c.x + bgha[g]; vh[g][1] = c.y + bgha[g];
                    vh[g][2] = d.x + bgha[g]; vh[g][3] = d.y + bgha[g];
                }
                float4 go4 = *(const float4*)(ghR + hc * 8 + ph * 4);
                float go[4] = { go4.x, go4.y, go4.z, go4.w };
                float hn[4];
                #pragma unroll
                for (int r = 0; r < 4; r++) {
                    float rr = sigm(vi[0][r] + vh[0][r]);
                    float zz = sigm(vi[1][r] + vh[1][r]);
                    float nn = tanhf(vi[2][r] + rr * vh[2][r]);
                    hn[r] = (1.f - zz) * nn + zz * go[r];
                }
                ull lo = ((ull)__float_as_uint(hn[1]) << 32) | (ull)__float_as_uint(hn[0]);
                ull hi = ((ull)__float_as_uint(hn[3]) << 32) | (ull)__float_as_uint(hn[2]);
                float* dp = ghW + hc * 8 + ph * 4;
                ((ull*)dp)[0] = lo; ((ull*)dp)[1] = hi;
                #pragma unroll
                for (int pr = 0; pr < 4; pr++) {
                    if (pr != q) {
                        st_peer64(dp, (unsigned)pr, lo);
                        st_peer64(dp + 2, (unsigned)pr, hi);
                    }
                }
            }
            EXCHANGE();
            gpb ^= 1;
        }
    }
    CLUSTER_SYNC();   // no CTA exits while peers' DSMEM stores may be in flight
}

// ==================== launch ====================
extern "C" void kernel_launch(void* const* d_in, const int* in_sizes, int n_in,
                              void* d_out, int out_size)
{
    const float* z     = (const float*)d_in[0];
    const float* nf    = (const float*)d_in[1];
    const float* u     = (const float*)d_in[2];
    const float* Wih_n = (const float*)d_in[3];
    const float* Whh_n = (const float*)d_in[4];
    const float* bih_n = (const float*)d_in[5];
    const float* bhh_n = (const float*)d_in[6];
    const float* Wih_g = (const float*)d_in[7];
    const float* Whh_g = (const float*)d_in[8];
    const float* bih_g = (const float*)d_in[9];
    const float* bhh_g = (const float*)d_in[10];
    const float* Ws1   = (const float*)d_in[11];
    const float* bs1   = (const float*)d_in[12];
    const float* Ws2   = (const float*)d_in[13];
    const float* bs2   = (const float*)d_in[14];
    float* out = (float*)d_out;

    const long total = 262144L * 3 + 1024 * 3 + 7168 * 2 + 16384
                     + BB * NN + TT + BB * NN * FF + BB * NN * NN + BB * NN;
    int blocks = (int)((total + 255) / 256);
    prep_kernel<<<blocks, 256>>>(nf, Wih_n, Whh_n, bih_n, bhh_n,
                                 Wih_g, Whh_g, bih_g, bhh_g, Ws1, out);

    cudaFuncSetAttribute(chain_kernel,
                         cudaFuncAttributeMaxDynamicSharedMemorySize, SMEM_BYTES);
    chain_kernel<<<NCTA, NT, SMEM_BYTES>>>(z, u, bs1, Ws2, bs2, out);
}

// round 12
// speedup vs baseline: 1.4251x; 1.0676x over previous
#include <cuda_runtime.h>
#include <math.h>

// ---------------- problem constants ----------------
#define BB 256
#define NN 32
#define HH 256
#define FF 7
#define TT 496
#define RR 8                 // batch rows per 4-CTA cluster
#define NCLUST (BB / RR)     // 32 clusters
#define NCTA (NCLUST * 4)    // 128 CTAs
#define NT 512
#define KQN 32               // k per octant (8-way K split, node gemm)
#define KQG 64               // k per quarter (graph gemm)
#define EPSF 1.1920929e-07f

typedef unsigned long long ull;

// ---------------- device scratch ----------------
// gate-interleaved layouts: local col index lc = hcol*4 + gate
__device__ float g_Wc4[4 * HH * 256];    // node combined weights [q][k][lc]
__device__ float g_Wgi4[4 * HH * 256];   // graph Wih [q][k][lc], gate3 = 0
__device__ float g_Wgh4[4 * HH * 256];   // graph Whh [q][k][lc], gate3 = 0
__device__ float g_bv4[4 * 256];         // node combined bias
__device__ float g_bgi4[4 * 256];        // graph ih bias (gate3 = 0)
__device__ float g_bgh4[4 * 256];        // graph hh bias (gate3 = 0)
__device__ float g_PQi4[4 * FF * 256];   // one-hot(i) gathers (gate3 = 0)
__device__ float g_PQj4[4 * FF * 256];
__device__ float g_Ws1T[HH * 64];        // Ws1 transposed [k][u]
__device__ int   g_idx[BB * NN];
__device__ int   g_rd[TT];
__device__ int   g_cd[TT];

// output layout (float32): [x 57344][adj 262144][batch 8192]
#define OUT_X 0
#define OUT_ADJ 57344
#define OUT_BATCH 319488

// ==================== prep kernel ====================
__global__ void prep_kernel(
    const float* __restrict__ nf,
    const float* __restrict__ Wih_n, const float* __restrict__ Whh_n,
    const float* __restrict__ bih_n, const float* __restrict__ bhh_n,
    const float* __restrict__ Wih_g, const float* __restrict__ Whh_g,
    const float* __restrict__ bih_g, const float* __restrict__ bhh_g,
    const float* __restrict__ Ws1,
    float* __restrict__ out)
{
    long t = (long)blockIdx.x * blockDim.x + threadIdx.x;

    if (t < 262144) {   // g_Wc4: [q][k][col*4+g]
        int q = (int)(t >> 16), k = (int)((t >> 8) & 255), lc = (int)(t & 255);
        int g = lc & 3, col = lc >> 2, hc = q * 64 + col;
        float v;
        if (g == 0)      v = Wih_n[hc * 270 + 14 + k] + Whh_n[hc * 256 + k];
        else if (g == 1) v = Wih_n[(256 + hc) * 270 + 14 + k] + Whh_n[(256 + hc) * 256 + k];
        else if (g == 2) v = Wih_n[(512 + hc) * 270 + 14 + k];
        else             v = Whh_n[(512 + hc) * 256 + k];
        g_Wc4[t] = v; return;
    }
    t -= 262144;
    if (t < 262144) {   // g_Wgi4
        int q = (int)(t >> 16), k = (int)((t >> 8) & 255), lc = (int)(t & 255);
        int g = lc & 3, col = lc >> 2, hc = q * 64 + col;
        g_Wgi4[t] = (g < 3) ? Wih_g[(g * 256 + hc) * 256 + k] : 0.f; return;
    }
    t -= 262144;
    if (t < 262144) {   // g_Wgh4
        int q = (int)(t >> 16), k = (int)((t >> 8) & 255), lc = (int)(t & 255);
        int g = lc & 3, col = lc >> 2, hc = q * 64 + col;
        g_Wgh4[t] = (g < 3) ? Whh_g[(g * 256 + hc) * 256 + k] : 0.f; return;
    }
    t -= 262144;
    if (t < 1024) {     // g_bv4
        int q = (int)(t >> 8), lc = (int)(t & 255);
        int g = lc & 3, col = lc >> 2, hc = q * 64 + col;
        float v;
        if (g == 0)      v = bih_n[hc] + bhh_n[hc];
        else if (g == 1) v = bih_n[256 + hc] + bhh_n[256 + hc];
        else if (g == 2) v = bih_n[512 + hc];
        else             v = bhh_n[512 + hc];
        g_bv4[t] = v; return;
    }
    t -= 1024;
    if (t < 1024) {     // g_bgi4
        int q = (int)(t >> 8), lc = (int)(t & 255);
        int g = lc & 3, col = lc >> 2, hc = q * 64 + col;
        g_bgi4[t] = (g < 3) ? bih_g[g * 256 + hc] : 0.f; return;
    }
    t -= 1024;
    if (t < 1024) {     // g_bgh4
        int q = (int)(t >> 8), lc = (int)(t & 255);
        int g = lc & 3, col = lc >> 2, hc = q * 64 + col;
        g_bgh4[t] = (g < 3) ? bhh_g[g * 256 + hc] : 0.f; return;
    }
    t -= 1024;
    if (t < 7168) {     // g_PQi4: [q][f][lc]
        int q = (int)(t / 1792), rem = (int)(t % 1792);
        int f = rem >> 8, lc = rem & 255;
        int g = lc & 3, col = lc >> 2, hc = q * 64 + col;
        g_PQi4[t] = (g < 3) ? Wih_n[(g * 256 + hc) * 270 + f] : 0.f; return;
    }
    t -= 7168;
    if (t < 7168) {     // g_PQj4
        int q = (int)(t / 1792), rem = (int)(t % 1792);
        int f = rem >> 8, lc = rem & 255;
        int g = lc & 3, col = lc >> 2, hc = q * 64 + col;
        g_PQj4[t] = (g < 3) ? Wih_n[(g * 256 + hc) * 270 + 7 + f] : 0.f; return;
    }
    t -= 7168;
    if (t < 16384) {    // W1T [k][u]
        int k = (int)(t >> 6), u = (int)(t & 63);
        g_Ws1T[t] = Ws1[u * 256 + k]; return;
    }
    t -= 16384;
    if (t < BB * NN) {  // argmax one-hot
        const float* p = nf + t * FF;
        int best = 0;
        #pragma unroll
        for (int f = 0; f < FF; f++) if (p[f] > 0.5f) best = f;
        g_idx[t] = best; return;
    }
    t -= BB * NN;
    if (t < TT) {       // anti-diagonal placement
        int m = (int)t;
        int d = (int)((1.0 + sqrt(1.0 + 8.0 * (double)m)) * 0.5);
        while (d * (d - 1) / 2 > m) d--;
        while ((d + 1) * d / 2 <= m) d++;
        int rr = m - d * (d - 1) / 2;
        g_rd[m] = rr; g_cd[m] = rr + NN - d; return;
    }
    t -= TT;
    if (t < BB * NN * FF) { out[OUT_X + t] = nf[t]; return; }
    t -= BB * NN * FF;
    if (t < BB * NN * NN) { out[OUT_ADJ + t] = 0.f; return; }
    t -= BB * NN * NN;
    if (t < BB * NN) { out[OUT_BATCH + t] = (float)(t >> 5); return; }
}

// ==================== helpers ====================
__device__ __forceinline__ float fex2(float x) {
    float r; asm("ex2.approx.ftz.f32 %0, %1;" : "=f"(r) : "f"(x)); return r;
}
__device__ __forceinline__ float frcp(float x) {
    float r; asm("rcp.approx.ftz.f32 %0, %1;" : "=f"(r) : "f"(x)); return r;
}
__device__ __forceinline__ float sigm(float x) {
    return frcp(1.f + fex2(-1.4426950408889634f * x));
}
__device__ __forceinline__ float ftanh(float x) {
    return 1.f - 2.f * frcp(1.f + fex2(2.8853900817779268f * x));
}

__device__ __forceinline__ void ffma2(ull& d, ull a, ull b) {
    asm("fma.rn.f32x2 %0, %1, %2, %0;" : "+l"(d) : "l"(a), "l"(b));
}
__device__ __forceinline__ void fadd2(ull& d, ull a) {
    asm("add.rn.f32x2 %0, %0, %1;" : "+l"(d) : "l"(a));
}
__device__ __forceinline__ ull dup2(float w) {
    ull r;
    asm("mov.b64 %0, {%1, %1};" : "=l"(r) : "r"(__float_as_uint(w)));
    return r;
}
__device__ __forceinline__ float2 unpk(ull v) {
    float2 r;
    r.x = __uint_as_float((unsigned)(v & 0xffffffffu));
    r.y = __uint_as_float((unsigned)(v >> 32));
    return r;
}
__device__ __forceinline__ void st_peer64(float* p, unsigned peer, ull bits) {
    unsigned la = (unsigned)__cvta_generic_to_shared(p);
    unsigned ra;
    asm volatile("mapa.shared::cluster.u32 %0, %1, %2;" : "=r"(ra) : "r"(la), "r"(peer));
    asm volatile("st.shared::cluster.b64 [%0], %1;" :: "r"(ra), "l"(bits) : "memory");
}
__device__ __forceinline__ void st_peer32(unsigned laddr, unsigned peer, float v) {
    unsigned ra;
    asm volatile("mapa.shared::cluster.u32 %0, %1, %2;" : "=r"(ra) : "r"(laddr), "r"(peer));
    asm volatile("st.shared::cluster.b32 [%0], %1;" :: "r"(ra), "r"(__float_as_uint(v)) : "memory");
}
__device__ __forceinline__ void mbar_init(unsigned addr, unsigned cnt) {
    asm volatile("mbarrier.init.shared.b64 [%0], %1;" :: "r"(addr), "r"(cnt) : "memory");
}
__device__ __forceinline__ void mbar_arrive_cluster(unsigned laddr, unsigned rank) {
    unsigned ra;
    asm volatile("mapa.shared::cluster.u32 %0, %1, %2;" : "=r"(ra) : "r"(laddr), "r"(rank));
    asm volatile("mbarrier.arrive.release.cluster.shared::cluster.b64 _, [%0];"
                 :: "r"(ra) : "memory");
}
__device__ __forceinline__ void mbar_wait(unsigned addr, unsigned parity) {
    asm volatile(
        "{\n\t.reg .pred P1;\n\t"
        "WAIT_LOOP_%=:\n\t"
        "mbarrier.try_wait.parity.acquire.cluster.shared::cta.b64 P1, [%0], %1, 0x989680;\n\t"
        "@P1 bra.uni WAIT_DONE_%=;\n\t"
        "bra.uni WAIT_LOOP_%=;\n\t"
        "WAIT_DONE_%=:\n\t}"
        :: "r"(addr), "r"(parity) : "memory");
}
#define CLUSTER_SYNC() do { \
    asm volatile("barrier.cluster.arrive.aligned;" ::: "memory"); \
    asm volatile("barrier.cluster.wait.aligned;" ::: "memory"); } while (0)

// two alternating mbarriers; all 512 threads reach this at the same points
#define EXCHANGE() do { \
    __syncthreads(); \
    unsigned mb_ = mbarB32 + (unsigned)((xstep & 1) * 8); \
    if (t < 4) mbar_arrive_cluster(mb_, (unsigned)t); \
    mbar_wait(mb_, (unsigned)((xstep >> 1) & 1)); \
    xstep++; \
} while (0)

// ---- gemm core: one thread owns 4 gate-cols of one h-col ----
// acc[g*4 + p] = f32x2 over rows (2p, 2p+1), gate g.
__device__ __forceinline__ void gbody(const float4 w, const float* __restrict__ hk,
                                      ull acc[16])
{
    ulonglong2 h01 = *(const ulonglong2*)(hk);
    ulonglong2 h23 = *(const ulonglong2*)(hk + 4);
    ull wd;
    wd = dup2(w.x);
    ffma2(acc[0], wd, h01.x); ffma2(acc[1], wd, h01.y);
    ffma2(acc[2], wd, h23.x); ffma2(acc[3], wd, h23.y);
    wd = dup2(w.y);
    ffma2(acc[4], wd, h01.x); ffma2(acc[5], wd, h01.y);
    ffma2(acc[6], wd, h23.x); ffma2(acc[7], wd, h23.y);
    wd = dup2(w.z);
    ffma2(acc[8],  wd, h01.x); ffma2(acc[9],  wd, h01.y);
    ffma2(acc[10], wd, h23.x); ffma2(acc[11], wd, h23.y);
    wd = dup2(w.w);
    ffma2(acc[12], wd, h01.x); ffma2(acc[13], wd, h01.y);
    ffma2(acc[14], wd, h23.x); ffma2(acc[15], wd, h23.y);
}

// streamed gemm over NK k-rows, weights from global (stride 256 floats/k)
// 8-deep register prefetch: ~320 cyc of compute per block covers L2 latency.
template <int NK>
__device__ __forceinline__ void gemm_glob(const float* __restrict__ Wp,
                                          const float* __restrict__ hq, ull acc[16])
{
    float4 wb[8];
    #pragma unroll
    for (int x = 0; x < 8; x++) wb[x] = *(const float4*)(Wp + x * 256);
    #pragma unroll
    for (int blk = 0; blk < NK / 8; blk++) {
        float4 wc[8];
        #pragma unroll
        for (int x = 0; x < 8; x++) wc[x] = wb[x];
        if (blk + 1 < NK / 8) {
            const float* np = Wp + (blk + 1) * 8 * 256;
            #pragma unroll
            for (int x = 0; x < 8; x++) wb[x] = *(const float4*)(np + x * 256);
        }
        const float* hkb = hq + blk * 8 * 8;
        #pragma unroll
        for (int x = 0; x < 8; x++) gbody(wc[x], hkb + x * 8, acc);
    }
}

// ---------------- smem layout (float offsets) ----------------
#define SO_WC   0                          // 2 octants resident: 2*32*256 = 16384
#define SO_W1L  (SO_WC + 2 * KQN * 256)    // 16384  W1T local slice [c][u] 64x64
#define SO_HA   (SO_W1L + 4096)            // 20480
#define SO_HB   (SO_HA + 2048)             // 22528
#define SO_GA   (SO_HB + 2048)             // 24576
#define SO_GB   (SO_GA + 2048)             // 26624
#define SO_RED  (SO_GB + 2048)             // 28672  64 slots x 256 floats
#define SO_PQI  (SO_RED + 16384)           // 45056
#define SO_PQJ  (SO_PQI + 1792)            // 46848
#define SO_PB   (SO_PQJ + 1792)            // 48640  score partials 2 buf x 4 src x 128
#define SO_SP4  (SO_PB + 1024)             // 49664  4 warp partials
#define SO_IDX  (SO_SP4 + 4)               // 49668  256 ints
#define SO_MBAR (SO_IDX + 256)             // 49924  2 mbarriers (8B each)
#define SMEM_FLOATS (SO_MBAR + 4)          // 49928
#define SMEM_BYTES (SMEM_FLOATS * 4)       // 199712

// ==================== main chain kernel ====================
__global__ void __launch_bounds__(NT, 1) __cluster_dims__(4, 1, 1)
chain_kernel(const float* __restrict__ z, const float* __restrict__ uin,
             const float* __restrict__ bs1, const float* __restrict__ Ws2,
             const float* __restrict__ bs2, float* __restrict__ out)
{
    extern __shared__ float sm[];
    float* sWc  = sm + SO_WC;
    float* sW1L = sm + SO_W1L;
    float* hBuf[2] = { sm + SO_HA, sm + SO_HB };
    float* gBuf[2] = { sm + SO_GA, sm + SO_GB };
    float* sred = sm + SO_RED;
    float* sPQi = sm + SO_PQI;
    float* sPQj = sm + SO_PQJ;
    float* sPB  = sm + SO_PB;
    float* sp4  = sm + SO_SP4;
    int*   sidx = (int*)(sm + SO_IDX);

    const int t = threadIdx.x;
    const int q = blockIdx.x & 3;
    const int cid = blockIdx.x >> 2;
    const int b0 = cid * RR;
    const unsigned sb32 = (unsigned)__cvta_generic_to_shared(sm);
    const unsigned mbarB32 = sb32 + SO_MBAR * 4;

    const float* WcG  = g_Wc4  + q * 65536;
    const float* WgiG = g_Wgi4 + q * 65536;
    const float* WghG = g_Wgh4 + q * 65536;

    // ---- init smem ----
    for (int x = t; x < 2 * KQN * 256; x += NT) sWc[x] = WcG[x];  // octants 0,1 resident
    for (int x = t; x < 4096; x += NT) sW1L[x] = g_Ws1T[q * 4096 + x];
    for (int x = t; x < FF * 256; x += NT) {
        sPQi[x] = g_PQi4[q * FF * 256 + x];
        sPQj[x] = g_PQj4[q * FF * 256 + x];
    }
    for (int x = t; x < 2048; x += NT) {      // graph h init [k][8]
        int k = x >> 3, r = x & 7;
        gBuf[0][x] = z[(b0 + r) * HH + k];
    }
    if (t < 256) sidx[t] = g_idx[b0 * NN + t];
    if (t == 0) {
        mbar_init(mbarB32, 4);
        mbar_init(mbarB32 + 8, 4);
    }

    // gemm role: 4 gate-cols of one h-col, one octant
    const int col = t & 63;
    const int oct = t >> 6;
    // reduce/activation role (t < 256): rowpair p, column col
    const int p   = oct & 3;                // rowpair 0..3 (rows 2p, 2p+1)
    const int sel = p & 1;                  // ull element inside staged pair
    const int sh  = p >> 1;                 // staged slot half
    const int hc  = q * 64 + col;
    // score-partial role (all 512): unit pu, row prow
    const int pu = t & 63;
    const int prow = t >> 6;                // 0..7
    // finalize constants (t < 128)
    const float b1r  = bs1[t & 63];
    const float w2r  = Ws2[t & 63];
    const float bs2v = *bs2;

    // reduce-thread bias constants (t < 256)
    float bva[4]  = {0,0,0,0};
    float bgia[3] = {0,0,0};
    float bgha[3] = {0,0,0};
    if (t < 256) {
        float4 b;
        b = *(const float4*)(g_bv4  + q * 256 + col * 4);
        bva[0]=b.x; bva[1]=b.y; bva[2]=b.z; bva[3]=b.w;
        b = *(const float4*)(g_bgi4 + q * 256 + col * 4);
        bgia[0]=b.x; bgia[1]=b.y; bgia[2]=b.z;
        b = *(const float4*)(g_bgh4 + q * 256 + col * 4);
        bgha[0]=b.x; bgha[1]=b.y; bgha[2]=b.z;
    }
    __syncthreads();
    CLUSTER_SYNC();      // mbarrier inits + smem visible cluster-wide

    int pb = 0, gpb = 0;
    int xstep = 0;       // exchange counter (selects barrier + parity)

    for (int i = 0; i < NN - 1; i++) {
        pb = 0;
        {   // node_h := graph_h
            const float* gs = gBuf[gpb];
            float* d = hBuf[0];
            for (int x = t; x < 2048; x += NT) d[x] = gs[x];
        }
        __syncthreads();

        int fiR[2];
        if (t < 256) {
            fiR[0] = sidx[(2 * p) * NN + i];
            fiR[1] = sidx[(2 * p + 1) * NN + i];
        }

        for (int j = i + 1; j < NN; j++) {
            float* hR = hBuf[pb];
            float* hW = hBuf[pb ^ 1];
            const int pbsel = xstep & 1;     // partial-buffer parity for THIS step

            // ---- node gemm: octant oct (0,1 resident in smem) ----
            ull acc[16];
            #pragma unroll
            for (int x = 0; x < 16; x++) acc[x] = 0ull;
            const float* hq = hR + oct * KQN * 8;
            if (oct <= 1) {
                const float* wp = sWc + oct * KQN * 256 + col * 4;
                #pragma unroll 4
                for (int k = 0; k < KQN; k++)
                    gbody(*(const float4*)(wp + k * 256), hq + k * 8, acc);
            } else {
                gemm_glob<KQN>(WcG + oct * KQN * 256 + col * 4, hq, acc);
            }
            // stage partials: slot = oct*8 + g*2 + pp
            #pragma unroll
            for (int g = 0; g < 4; g++) {
                #pragma unroll
                for (int pp = 0; pp < 2; pp++) {
                    *(ulonglong2*)(sred + ((oct * 8 + g * 2 + pp) * 256 + col * 4)) =
                        make_ulonglong2(acc[g * 4 + 2 * pp], acc[g * 4 + 2 * pp + 1]);
                }
            }
            __syncthreads();

            // ---- reduce + in-register GRU activation (t < 256, 2 rows each) ----
            if (t < 256) {
                float vg[4][2];
                #pragma unroll
                for (int g = 0; g < 4; g++) {
                    ull a = 0ull;
                    #pragma unroll
                    for (int o = 0; o < 8; o++) {
                        ull v = *(const ull*)
                            (sred + ((o * 8 + g * 2 + sh) * 256 + col * 4 + 2 * sel));
                        fadd2(a, v);
                    }
                    float2 f = unpk(a);
                    vg[g][0] = f.x + bva[g];
                    vg[g][1] = f.y + bva[g];
                }
                #pragma unroll
                for (int s = 0; s < 2; s++) {
                    int rb = 2 * p + s;
                    int fj = sidx[rb * NN + j];
                    float4 pi = *(const float4*)(sPQi + fiR[s] * 256 + col * 4);
                    float4 pj = *(const float4*)(sPQj + fj * 256 + col * 4);
                    vg[0][s] += pi.x + pj.x;
                    vg[1][s] += pi.y + pj.y;
                    vg[2][s] += pi.z + pj.z;
                }
                float2 hov = unpk(*(const ull*)(hR + hc * 8 + 2 * p));
                float ho[2] = { hov.x, hov.y };
                float hn[2];
                #pragma unroll
                for (int s = 0; s < 2; s++) {
                    float gr = sigm(vg[0][s]);
                    float gz = sigm(vg[1][s]);
                    float gn = ftanh(vg[2][s] + gr * vg[3][s]);
                    hn[s] = (1.f - gz) * gn + gz * ho[s];
                }
                ull lo = ((ull)__float_as_uint(hn[1]) << 32) | (ull)__float_as_uint(hn[0]);
                float* dp = hW + hc * 8 + 2 * p;
                *(ull*)dp = lo;
                #pragma unroll
                for (int pr = 0; pr < 4; pr++)
                    if (pr != q) st_peer64(dp, (unsigned)pr, lo);
            }
            __syncthreads();   // local h slice complete

            // ---- local score partials over own 64 cols (overlaps exchange) ----
            {
                float a0 = 0.f, a1 = 0.f;
                const float* wp = sW1L + pu;               // [c][u] stride 64
                const float* hp = hW + (q * 64) * 8 + prow; // [c] stride 8 (broadcast)
                #pragma unroll 8
                for (int c = 0; c < 64; c += 2) {
                    a0 = fmaf(wp[c * 64],       hp[c * 8],       a0);
                    a1 = fmaf(wp[(c + 1) * 64], hp[(c + 1) * 8], a1);
                }
                float pv = a0 + a1;
                int tr = prow >> 1, rl = prow & 1;          // owner CTA, local row
                unsigned laddr = sb32 +
                    (unsigned)((SO_PB + pbsel * 512 + q * 128 + pu * 2 + rl) * 4);
                st_peer32(laddr, (unsigned)tr, pv);
            }
            EXCHANGE();

            // ---- finalize score + edge for own rows 2q, 2q+1 (t < 128) ----
            if (t < 128) {
                int u = t & 63, rl = (t >> 6) & 1;
                const float* pbp = sPB + pbsel * 512;
                float ssum = pbp[u * 2 + rl] + pbp[128 + u * 2 + rl]
                           + pbp[256 + u * 2 + rl] + pbp[384 + u * 2 + rl];
                float hid = fmaxf(ssum + b1r, 0.f) * w2r;
                #pragma unroll
                for (int o = 16; o; o >>= 1)
                    hid += __shfl_down_sync(0xffffffffu, hid, o);
                if ((t & 31) == 0) sp4[t >> 5] = hid;
                asm volatile("bar.sync 1, 128;" ::: "memory");
                if (t < 2) {
                    float s = sp4[2 * t] + sp4[2 * t + 1] + bs2v;
                    float prob = sigm(s);
                    int m = i * (NN - 1) - (i * (i - 1)) / 2 + (j - i - 1);
                    int b = b0 + 2 * q + t;
                    float uu = uin[b * TT + m];
                    float pc = fminf(fmaxf(prob, EPSF), 1.f - EPSF);
                    float e;
                    if (pc < 0.499f || pc > 0.501f) {
                        e = (log1pf(-pc + uu * (2.f * pc - 1.f)) - log1pf(-pc))
                          / (logf(pc) - log1pf(-pc));
                    } else {
                        e = uu;
                    }
                    int rr = g_rd[m], cc = g_cd[m];
                    float* adj = out + OUT_ADJ + b * (NN * NN);
                    adj[rr * NN + cc] = e;
                    adj[cc * NN + rr] = e;
                }
            }
            pb ^= 1;
        }

        // ---- graph GRU (one pass; octants 0-3 = Wgi, 4-7 = Wgh) ----
        if (i < NN - 2) {
            const float* hfin = hBuf[pb];
            const float* ghR = gBuf[gpb];
            float* ghW = gBuf[gpb ^ 1];

            {
                ull acc[16];
                #pragma unroll
                for (int x = 0; x < 16; x++) acc[x] = 0ull;
                if (oct < 4)
                    gemm_glob<KQG>(WgiG + oct * KQG * 256 + col * 4,
                                   hfin + oct * KQG * 8, acc);
                else
                    gemm_glob<KQG>(WghG + (oct - 4) * KQG * 256 + col * 4,
                                   ghR + (oct - 4) * KQG * 8, acc);
                #pragma unroll
                for (int g = 0; g < 4; g++) {
                    #pragma unroll
                    for (int pp = 0; pp < 2; pp++) {
                        *(ulonglong2*)(sred + ((oct * 8 + g * 2 + pp) * 256 + col * 4)) =
                            make_ulonglong2(acc[g * 4 + 2 * pp], acc[g * 4 + 2 * pp + 1]);
                    }
                }
            }
            __syncthreads();

            if (t < 256) {
                float vi[3][2], vh[3][2];
                #pragma unroll
                for (int g = 0; g < 3; g++) {
                    ull ai = 0ull, ah = 0ull;
                    #pragma unroll
                    for (int o = 0; o < 4; o++) {
                        ull v = *(const ull*)
                            (sred + ((o * 8 + g * 2 + sh) * 256 + col * 4 + 2 * sel));
                        fadd2(ai, v);
                    }
                    #pragma unroll
                    for (int o = 4; o < 8; o++) {
                        ull v = *(const ull*)
                            (sred + ((o * 8 + g * 2 + sh) * 256 + col * 4 + 2 * sel));
                        fadd2(ah, v);
                    }
                    float2 a = unpk(ai);
                    vi[g][0] = a.x + bgia[g]; vi[g][1] = a.y + bgia[g];
                    float2 c = unpk(ah);
                    vh[g][0] = c.x + bgha[g]; vh[g][1] = c.y + bgha[g];
                }
                float2 gov = unpk(*(const ull*)(ghR + hc * 8 + 2 * p));
                float go[2] = { gov.x, gov.y };
                float hn[2];
                #pragma unroll
                for (int s = 0; s < 2; s++) {
                    float rr = sigm(vi[0][s] + vh[0][s]);
                    float zz = sigm(vi[1][s] + vh[1][s]);
                    float nn = ftanh(vi[2][s] + rr * vh[2][s]);
                    hn[s] = (1.f - zz) * nn + zz * go[s];
                }
                ull lo = ((ull)__float_as_uint(hn[1]) << 32) | (ull)__float_as_uint(hn[0]);
                float* dp = ghW + hc * 8 + 2 * p;
                *(ull*)dp = lo;
                #pragma unroll
                for (int pr = 0; pr < 4; pr++)
                    if (pr != q) st_peer64(dp, (unsigned)pr, lo);
            }
            EXCHANGE();
            gpb ^= 1;
        }
    }
    CLUSTER_SYNC();   // no CTA exits while peers' DSMEM stores may be in flight
}

// ==================== launch ====================
extern "C" void kernel_launch(void* const* d_in, const int* in_sizes, int n_in,
                              void* d_out, int out_size)
{
    const float* z     = (const float*)d_in[0];
    const float* nf    = (const float*)d_in[1];
    const float* u     = (const float*)d_in[2];
    const float* Wih_n = (const float*)d_in[3];
    const float* Whh_n = (const float*)d_in[4];
    const float* bih_n = (const float*)d_in[5];
    const float* bhh_n = (const float*)d_in[6];
    const float* Wih_g = (const float*)d_in[7];
    const float* Whh_g = (const float*)d_in[8];
    const float* bih_g = (const float*)d_in[9];
    const float* bhh_g = (const float*)d_in[10];
    const float* Ws1   = (const float*)d_in[11];
    const float* bs1   = (const float*)d_in[12];
    const float* Ws2   = (const float*)d_in[13];
    const float* bs2   = (const float*)d_in[14];
    float* out = (float*)d_out;

    const long total = 262144L * 3 + 1024 * 3 + 7168 * 2 + 16384
                     + BB * NN + TT + BB * NN * FF + BB * NN * NN + BB * NN;
    int blocks = (int)((total + 255) / 256);
    prep_kernel<<<blocks, 256>>>(nf, Wih_n, Whh_n, bih_n, bhh_n,
                                 Wih_g, Whh_g, bih_g, bhh_g, Ws1, out);

    cudaFuncSetAttribute(chain_kernel,
                         cudaFuncAttributeMaxDynamicSharedMemorySize, SMEM_BYTES);
    chain_kernel<<<NCTA, NT, SMEM_BYTES>>>(z, u, bs1, Ws2, bs2, out);
}

// round 13
// speedup vs baseline: 1.5221x; 1.0680x over previous
#include <cuda_runtime.h>
#include <math.h>

// ---------------- problem constants ----------------
#define BB 256
#define NN 32
#define HH 256
#define FF 7
#define TT 496
#define RR 8                 // batch rows per 4-CTA cluster
#define NCLUST (BB / RR)     // 32 clusters
#define NCTA (NCLUST * 4)    // 128 CTAs
#define NT 512
#define KQN 32               // k per octant (8-way K split, node gemm)
#define KQG 64               // k per quarter (graph gemm)
#define EPSF 1.1920929e-07f

typedef unsigned long long ull;

// ---------------- device scratch ----------------
// gate-interleaved layouts: local col index lc = hcol*4 + gate
__device__ float g_Wc4[4 * HH * 256];    // node combined weights [q][k][lc]
__device__ float g_Wgi4[4 * HH * 256];   // graph Wih [q][k][lc], gate3 = 0
__device__ float g_Wgh4[4 * HH * 256];   // graph Whh [q][k][lc], gate3 = 0
__device__ float g_bv4[4 * 256];         // node combined bias
__device__ float g_bgi4[4 * 256];        // graph ih bias (gate3 = 0)
__device__ float g_bgh4[4 * 256];        // graph hh bias (gate3 = 0)
__device__ float g_PQi4[4 * FF * 256];   // one-hot(i) gathers (gate3 = 0)
__device__ float g_PQj4[4 * FF * 256];
__device__ float g_Ws1T[HH * 64];        // Ws1 transposed [k][u]
__device__ int   g_idx[BB * NN];
__device__ int   g_rd[TT];
__device__ int   g_cd[TT];

// output layout (float32): [x 57344][adj 262144][batch 8192]
#define OUT_X 0
#define OUT_ADJ 57344
#define OUT_BATCH 319488

// ==================== prep kernel ====================
__global__ void prep_kernel(
    const float* __restrict__ nf,
    const float* __restrict__ Wih_n, const float* __restrict__ Whh_n,
    const float* __restrict__ bih_n, const float* __restrict__ bhh_n,
    const float* __restrict__ Wih_g, const float* __restrict__ Whh_g,
    const float* __restrict__ bih_g, const float* __restrict__ bhh_g,
    const float* __restrict__ Ws1,
    float* __restrict__ out)
{
    long t = (long)blockIdx.x * blockDim.x + threadIdx.x;

    if (t < 262144) {   // g_Wc4: [q][k][col*4+g]
        int q = (int)(t >> 16), k = (int)((t >> 8) & 255), lc = (int)(t & 255);
        int g = lc & 3, col = lc >> 2, hc = q * 64 + col;
        float v;
        if (g == 0)      v = Wih_n[hc * 270 + 14 + k] + Whh_n[hc * 256 + k];
        else if (g == 1) v = Wih_n[(256 + hc) * 270 + 14 + k] + Whh_n[(256 + hc) * 256 + k];
        else if (g == 2) v = Wih_n[(512 + hc) * 270 + 14 + k];
        else             v = Whh_n[(512 + hc) * 256 + k];
        g_Wc4[t] = v; return;
    }
    t -= 262144;
    if (t < 262144) {   // g_Wgi4
        int q = (int)(t >> 16), k = (int)((t >> 8) & 255), lc = (int)(t & 255);
        int g = lc & 3, col = lc >> 2, hc = q * 64 + col;
        g_Wgi4[t] = (g < 3) ? Wih_g[(g * 256 + hc) * 256 + k] : 0.f; return;
    }
    t -= 262144;
    if (t < 262144) {   // g_Wgh4
        int q = (int)(t >> 16), k = (int)((t >> 8) & 255), lc = (int)(t & 255);
        int g = lc & 3, col = lc >> 2, hc = q * 64 + col;
        g_Wgh4[t] = (g < 3) ? Whh_g[(g * 256 + hc) * 256 + k] : 0.f; return;
    }
    t -= 262144;
    if (t < 1024) {     // g_bv4
        int q = (int)(t >> 8), lc = (int)(t & 255);
        int g = lc & 3, col = lc >> 2, hc = q * 64 + col;
        float v;
        if (g == 0)      v = bih_n[hc] + bhh_n[hc];
        else if (g == 1) v = bih_n[256 + hc] + bhh_n[256 + hc];
        else if (g == 2) v = bih_n[512 + hc];
        else             v = bhh_n[512 + hc];
        g_bv4[t] = v; return;
    }
    t -= 1024;
    if (t < 1024) {     // g_bgi4
        int q = (int)(t >> 8), lc = (int)(t & 255);
        int g = lc & 3, col = lc >> 2, hc = q * 64 + col;
        g_bgi4[t] = (g < 3) ? bih_g[g * 256 + hc] : 0.f; return;
    }
    t -= 1024;
    if (t < 1024) {     // g_bgh4
        int q = (int)(t >> 8), lc = (int)(t & 255);
        int g = lc & 3, col = lc >> 2, hc = q * 64 + col;
        g_bgh4[t] = (g < 3) ? bhh_g[g * 256 + hc] : 0.f; return;
    }
    t -= 1024;
    if (t < 7168) {     // g_PQi4: [q][f][lc]
        int q = (int)(t / 1792), rem = (int)(t % 1792);
        int f = rem >> 8, lc = rem & 255;
        int g = lc & 3, col = lc >> 2, hc = q * 64 + col;
        g_PQi4[t] = (g < 3) ? Wih_n[(g * 256 + hc) * 270 + f] : 0.f; return;
    }
    t -= 7168;
    if (t < 7168) {     // g_PQj4
        int q = (int)(t / 1792), rem = (int)(t % 1792);
        int f = rem >> 8, lc = rem & 255;
        int g = lc & 3, col = lc >> 2, hc = q * 64 + col;
        g_PQj4[t] = (g < 3) ? Wih_n[(g * 256 + hc) * 270 + 7 + f] : 0.f; return;
    }
    t -= 7168;
    if (t < 16384) {    // W1T [k][u]
        int k = (int)(t >> 6), u = (int)(t & 63);
        g_Ws1T[t] = Ws1[u * 256 + k]; return;
    }
    t -= 16384;
    if (t < BB * NN) {  // argmax one-hot
        const float* p = nf + t * FF;
        int best = 0;
        #pragma unroll
        for (int f = 0; f < FF; f++) if (p[f] > 0.5f) best = f;
        g_idx[t] = best; return;
    }
    t -= BB * NN;
    if (t < TT) {       // anti-diagonal placement
        int m = (int)t;
        int d = (int)((1.0 + sqrt(1.0 + 8.0 * (double)m)) * 0.5);
        while (d * (d - 1) / 2 > m) d--;
        while ((d + 1) * d / 2 <= m) d++;
        int rr = m - d * (d - 1) / 2;
        g_rd[m] = rr; g_cd[m] = rr + NN - d; return;
    }
    t -= TT;
    if (t < BB * NN * FF) { out[OUT_X + t] = nf[t]; return; }
    t -= BB * NN * FF;
    if (t < BB * NN * NN) { out[OUT_ADJ + t] = 0.f; return; }
    t -= BB * NN * NN;
    if (t < BB * NN) { out[OUT_BATCH + t] = (float)(t >> 5); return; }
}

// ==================== helpers ====================
__device__ __forceinline__ float fex2(float x) {
    float r; asm("ex2.approx.ftz.f32 %0, %1;" : "=f"(r) : "f"(x)); return r;
}
__device__ __forceinline__ float frcp(float x) {
    float r; asm("rcp.approx.ftz.f32 %0, %1;" : "=f"(r) : "f"(x)); return r;
}
__device__ __forceinline__ float sigm(float x) {
    return frcp(1.f + fex2(-1.4426950408889634f * x));
}
__device__ __forceinline__ float ftanh(float x) {
    return 1.f - 2.f * frcp(1.f + fex2(2.8853900817779268f * x));
}

__device__ __forceinline__ void ffma2(ull& d, ull a, ull b) {
    asm("fma.rn.f32x2 %0, %1, %2, %0;" : "+l"(d) : "l"(a), "l"(b));
}
__device__ __forceinline__ void fadd2(ull& d, ull a) {
    asm("add.rn.f32x2 %0, %0, %1;" : "+l"(d) : "l"(a));
}
__device__ __forceinline__ ull dup2(float w) {
    ull r;
    asm("mov.b64 %0, {%1, %1};" : "=l"(r) : "r"(__float_as_uint(w)));
    return r;
}
__device__ __forceinline__ float2 unpk(ull v) {
    float2 r;
    r.x = __uint_as_float((unsigned)(v & 0xffffffffu));
    r.y = __uint_as_float((unsigned)(v >> 32));
    return r;
}
__device__ __forceinline__ ull pk(float x, float y) {
    return ((ull)__float_as_uint(y) << 32) | (ull)__float_as_uint(x);
}
__device__ __forceinline__ void st_peer64(float* p, unsigned peer, ull bits) {
    unsigned la = (unsigned)__cvta_generic_to_shared(p);
    unsigned ra;
    asm volatile("mapa.shared::cluster.u32 %0, %1, %2;" : "=r"(ra) : "r"(la), "r"(peer));
    asm volatile("st.shared::cluster.b64 [%0], %1;" :: "r"(ra), "l"(bits) : "memory");
}
__device__ __forceinline__ void st_peer64a(unsigned laddr, unsigned peer, ull bits) {
    unsigned ra;
    asm volatile("mapa.shared::cluster.u32 %0, %1, %2;" : "=r"(ra) : "r"(laddr), "r"(peer));
    asm volatile("st.shared::cluster.b64 [%0], %1;" :: "r"(ra), "l"(bits) : "memory");
}
__device__ __forceinline__ void mbar_init(unsigned addr, unsigned cnt) {
    asm volatile("mbarrier.init.shared.b64 [%0], %1;" :: "r"(addr), "r"(cnt) : "memory");
}
__device__ __forceinline__ void mbar_arrive_cluster(unsigned laddr, unsigned rank) {
    unsigned ra;
    asm volatile("mapa.shared::cluster.u32 %0, %1, %2;" : "=r"(ra) : "r"(laddr), "r"(rank));
    asm volatile("mbarrier.arrive.release.cluster.shared::cluster.b64 _, [%0];"
                 :: "r"(ra) : "memory");
}
__device__ __forceinline__ void mbar_wait(unsigned addr, unsigned parity) {
    asm volatile(
        "{\n\t.reg .pred P1;\n\t"
        "WAIT_LOOP_%=:\n\t"
        "mbarrier.try_wait.parity.acquire.cluster.shared::cta.b64 P1, [%0], %1, 0x989680;\n\t"
        "@P1 bra.uni WAIT_DONE_%=;\n\t"
        "bra.uni WAIT_LOOP_%=;\n\t"
        "WAIT_DONE_%=:\n\t}"
        :: "r"(addr), "r"(parity) : "memory");
}
#define CLUSTER_SYNC() do { \
    asm volatile("barrier.cluster.arrive.aligned;" ::: "memory"); \
    asm volatile("barrier.cluster.wait.aligned;" ::: "memory"); } while (0)

// two alternating mbarriers; all 512 threads reach this at the same points
#define EXCHANGE() do { \
    __syncthreads(); \
    unsigned mb_ = mbarB32 + (unsigned)((xstep & 1) * 8); \
    if (t < 4) mbar_arrive_cluster(mb_, (unsigned)t); \
    mbar_wait(mb_, (unsigned)((xstep >> 1) & 1)); \
    xstep++; \
} while (0)

// ---- gemm core: one thread owns 4 gate-cols of one h-col ----
// acc[g*4 + p] = f32x2 over rows (2p, 2p+1), gate g.
__device__ __forceinline__ void gbody(const float4 w, const float* __restrict__ hk,
                                      ull acc[16])
{
    ulonglong2 h01 = *(const ulonglong2*)(hk);
    ulonglong2 h23 = *(const ulonglong2*)(hk + 4);
    ull wd;
    wd = dup2(w.x);
    ffma2(acc[0], wd, h01.x); ffma2(acc[1], wd, h01.y);
    ffma2(acc[2], wd, h23.x); ffma2(acc[3], wd, h23.y);
    wd = dup2(w.y);
    ffma2(acc[4], wd, h01.x); ffma2(acc[5], wd, h01.y);
    ffma2(acc[6], wd, h23.x); ffma2(acc[7], wd, h23.y);
    wd = dup2(w.z);
    ffma2(acc[8],  wd, h01.x); ffma2(acc[9],  wd, h01.y);
    ffma2(acc[10], wd, h23.x); ffma2(acc[11], wd, h23.y);
    wd = dup2(w.w);
    ffma2(acc[12], wd, h01.x); ffma2(acc[13], wd, h01.y);
    ffma2(acc[14], wd, h23.x); ffma2(acc[15], wd, h23.y);
}

// streamed gemm over NK k-rows, weights from global (stride 256 floats/k)
// 8-deep register prefetch covers L2 latency.
template <int NK>
__device__ __forceinline__ void gemm_glob(const float* __restrict__ Wp,
                                          const float* __restrict__ hq, ull acc[16])
{
    float4 wb[8];
    #pragma unroll
    for (int x = 0; x < 8; x++) wb[x] = *(const float4*)(Wp + x * 256);
    #pragma unroll
    for (int blk = 0; blk < NK / 8; blk++) {
        float4 wc[8];
        #pragma unroll
        for (int x = 0; x < 8; x++) wc[x] = wb[x];
        if (blk + 1 < NK / 8) {
            const float* np = Wp + (blk + 1) * 8 * 256;
            #pragma unroll
            for (int x = 0; x < 8; x++) wb[x] = *(const float4*)(np + x * 256);
        }
        const float* hkb = hq + blk * 8 * 8;
        #pragma unroll
        for (int x = 0; x < 8; x++) gbody(wc[x], hkb + x * 8, acc);
    }
}

// ---------------- smem layout (float offsets) ----------------
#define SO_WC   0                          // 2 octants resident: 16384
#define SO_W1L  (SO_WC + 2 * KQN * 256)    // 16384  W1T local slice [c][u] 64x64
#define SO_HA   (SO_W1L + 4096)            // 20480
#define SO_HB   (SO_HA + 2048)             // 22528
#define SO_GA   (SO_HB + 2048)             // 24576
#define SO_GB   (SO_GA + 2048)             // 26624
#define SO_RED  (SO_GB + 2048)             // 28672  64 slots x 256 floats
#define SO_PQI  (SO_RED + 16384)           // 45056
#define SO_PQJ  (SO_PQI + 1792)            // 46848
#define SO_PB   (SO_PQJ + 1792)            // 48640  score partials 2par x 8src x 64 ull
#define SO_SP4  (SO_PB + 2048)             // 50688  2 ull
#define SO_IDX  (SO_SP4 + 4)               // 50692  256 ints
#define SO_MBAR (SO_IDX + 256)             // 50948  2 mbarriers (8B aligned)
#define SMEM_FLOATS (SO_MBAR + 4)          // 50952
#define SMEM_BYTES (SMEM_FLOATS * 4)       // 203808

// ==================== main chain kernel ====================
__global__ void __launch_bounds__(NT, 1) __cluster_dims__(4, 1, 1)
chain_kernel(const float* __restrict__ z, const float* __restrict__ uin,
             const float* __restrict__ bs1, const float* __restrict__ Ws2,
             const float* __restrict__ bs2, float* __restrict__ out)
{
    extern __shared__ float sm[];
    float* sWc  = sm + SO_WC;
    float* sW1L = sm + SO_W1L;
    float* hBuf[2] = { sm + SO_HA, sm + SO_HB };
    float* gBuf[2] = { sm + SO_GA, sm + SO_GB };
    float* sred = sm + SO_RED;
    float* sPQi = sm + SO_PQI;
    float* sPQj = sm + SO_PQJ;
    float* sPB  = sm + SO_PB;
    ull*   sp4u = (ull*)(sm + SO_SP4);
    int*   sidx = (int*)(sm + SO_IDX);

    const int t = threadIdx.x;
    const int q = blockIdx.x & 3;
    const int cid = blockIdx.x >> 2;
    const int b0 = cid * RR;
    const unsigned sb32 = (unsigned)__cvta_generic_to_shared(sm);
    const unsigned mbarB32 = sb32 + SO_MBAR * 4;

    const float* WcG  = g_Wc4  + q * 65536;
    const float* WgiG = g_Wgi4 + q * 65536;
    const float* WghG = g_Wgh4 + q * 65536;

    // ---- init smem ----
    for (int x = t; x < 2 * KQN * 256; x += NT) sWc[x] = WcG[x];  // octants 0,1 resident
    for (int x = t; x < 4096; x += NT) sW1L[x] = g_Ws1T[q * 4096 + x];
    for (int x = t; x < FF * 256; x += NT) {
        sPQi[x] = g_PQi4[q * FF * 256 + x];
        sPQj[x] = g_PQj4[q * FF * 256 + x];
    }
    for (int x = t; x < 2048; x += NT) {      // graph h init [k][8]
        int k = x >> 3, r = x & 7;
        gBuf[0][x] = z[(b0 + r) * HH + k];
    }
    if (t < 256) sidx[t] = g_idx[b0 * NN + t];
    if (t == 0) {
        mbar_init(mbarB32, 4);
        mbar_init(mbarB32 + 8, 4);
    }

    // gemm role: 4 gate-cols of one h-col, one octant
    const int col = t & 63;
    const int oct = t >> 6;
    // reduce/activation role (t < 128): row-half ph (rows 4ph..4ph+3)
    const int ph = oct & 1;
    const int hc = q * 64 + col;
    // score-partial role (all 512): unit su, rowpair rp, c-half chalf
    const int su = t & 63;
    const int rp = (t >> 6) & 3;
    const int chalf = t >> 8;
    // finalize constants (t < 64)
    const float b1r  = bs1[t & 63];
    const float w2r  = Ws2[t & 63];
    const float bs2v = *bs2;

    // reduce-thread bias constants (t < 128)
    float bva[4]  = {0,0,0,0};
    float bgia[3] = {0,0,0};
    float bgha[3] = {0,0,0};
    if (t < 128) {
        float4 b;
        b = *(const float4*)(g_bv4  + q * 256 + col * 4);
        bva[0]=b.x; bva[1]=b.y; bva[2]=b.z; bva[3]=b.w;
        b = *(const float4*)(g_bgi4 + q * 256 + col * 4);
        bgia[0]=b.x; bgia[1]=b.y; bgia[2]=b.z;
        b = *(const float4*)(g_bgh4 + q * 256 + col * 4);
        bgha[0]=b.x; bgha[1]=b.y; bgha[2]=b.z;
    }
    __syncthreads();
    CLUSTER_SYNC();      // mbarrier inits + smem visible cluster-wide

    int pb = 0, gpb = 0;
    int xstep = 0;       // exchange counter (selects barrier + parity)

    for (int i = 0; i < NN - 1; i++) {
        pb = 0;
        {   // node_h := graph_h
            const float* gs = gBuf[gpb];
            float* d = hBuf[0];
            for (int x = t; x < 2048; x += NT) d[x] = gs[x];
        }
        __syncthreads();

        int fiR[4];
        if (t < 128) {
            #pragma unroll
            for (int r = 0; r < 4; r++) fiR[r] = sidx[(ph * 4 + r) * NN + i];
        }

        for (int j = i + 1; j < NN; j++) {
            float* hR = hBuf[pb];
            float* hW = hBuf[pb ^ 1];
            const int pbsel = xstep & 1;     // partial-buffer parity for THIS step

            // ---- node gemm: octant oct (0,1 resident in smem) ----
            ull acc[16];
            #pragma unroll
            for (int x = 0; x < 16; x++) acc[x] = 0ull;
            const float* hq = hR + oct * KQN * 8;
            if (oct <= 1) {
                const float* wp = sWc + oct * KQN * 256 + col * 4;
                #pragma unroll 4
                for (int k = 0; k < KQN; k++)
                    gbody(*(const float4*)(wp + k * 256), hq + k * 8, acc);
            } else {
                gemm_glob<KQN>(WcG + oct * KQN * 256 + col * 4, hq, acc);
            }
            // stage partials: slot = oct*8 + g*2 + pp
            #pragma unroll
            for (int g = 0; g < 4; g++) {
                #pragma unroll
                for (int pp = 0; pp < 2; pp++) {
                    *(ulonglong2*)(sred + ((oct * 8 + g * 2 + pp) * 256 + col * 4)) =
                        make_ulonglong2(acc[g * 4 + 2 * pp], acc[g * 4 + 2 * pp + 1]);
                }
            }
            __syncthreads();

            // ---- reduce + in-register GRU activation (t < 128, 4 rows each) ----
            if (t < 128) {
                ull s0[4], s1[4];
                #pragma unroll
                for (int g = 0; g < 4; g++) {
                    s0[g] = 0ull; s1[g] = 0ull;
                    #pragma unroll
                    for (int o = 0; o < 8; o++) {
                        ulonglong2 v = *(const ulonglong2*)
                            (sred + ((o * 8 + g * 2 + ph) * 256 + col * 4));
                        fadd2(s0[g], v.x); fadd2(s1[g], v.y);
                    }
                }
                float vg[4][4];
                #pragma unroll
                for (int g = 0; g < 4; g++) {
                    float2 a = unpk(s0[g]), b = unpk(s1[g]);
                    vg[g][0] = a.x + bva[g]; vg[g][1] = a.y + bva[g];
                    vg[g][2] = b.x + bva[g]; vg[g][3] = b.y + bva[g];
                }
                #pragma unroll
                for (int r = 0; r < 4; r++) {
                    int rb = ph * 4 + r;
                    int fj = sidx[rb * NN + j];
                    float4 pi = *(const float4*)(sPQi + fiR[r] * 256 + col * 4);
                    float4 pj = *(const float4*)(sPQj + fj * 256 + col * 4);
                    vg[0][r] += pi.x + pj.x;
                    vg[1][r] += pi.y + pj.y;
                    vg[2][r] += pi.z + pj.z;
                }
                float4 ho4 = *(const float4*)(hR + hc * 8 + ph * 4);
                float ho[4] = { ho4.x, ho4.y, ho4.z, ho4.w };
                float hn[4];
                #pragma unroll
                for (int r = 0; r < 4; r++) {
                    float gr = sigm(vg[0][r]);
                    float gz = sigm(vg[1][r]);
                    float gn = ftanh(vg[2][r] + gr * vg[3][r]);
                    hn[r] = (1.f - gz) * gn + gz * ho[r];
                }
                ull lo = pk(hn[0], hn[1]);
                ull hi = pk(hn[2], hn[3]);
                float* dp = hW + hc * 8 + ph * 4;
                ((ull*)dp)[0] = lo; ((ull*)dp)[1] = hi;
                #pragma unroll
                for (int pr = 0; pr < 4; pr++) {
                    if (pr != q) {
                        st_peer64(dp, (unsigned)pr, lo);
                        st_peer64(dp + 2, (unsigned)pr, hi);
                    }
                }
            }
            __syncthreads();   // local h slice complete

            // ---- packed score partials over own 64 cols, c-split (all 512) ----
            {
                ull sacc = 0ull;
                const float* wp = sW1L + chalf * 32 * 64 + su;          // stride 64
                const float* hp = hW + (q * 64 + chalf * 32) * 8 + 2 * rp;
                #pragma unroll 8
                for (int c = 0; c < 32; c++)
                    ffma2(sacc, dup2(wp[c * 64]), *(const ull*)(hp + c * 8));
                // destination: owner CTA rp, slot [chalf*4 + q][su]
                unsigned laddr = sb32 +
                    (unsigned)((SO_PB + pbsel * 1024 + chalf * 512 + q * 128 + su * 2) * 4);
                st_peer64a(laddr, (unsigned)rp, sacc);
            }
            EXCHANGE();

            // ---- finalize score + edge for own rows 2q, 2q+1 (t < 64) ----
            if (t < 64) {
                ull sum = 0ull;
                const ull* pbp = (const ull*)(sPB + pbsel * 1024);
                #pragma unroll
                for (int x = 0; x < 8; x++) fadd2(sum, pbp[x * 64 + t]);
                float2 s = unpk(sum);
                float hx = fmaxf(s.x + b1r, 0.f) * w2r;
                float hy = fmaxf(s.y + b1r, 0.f) * w2r;
                ull sc = pk(hx, hy);
                #pragma unroll
                for (int o = 16; o; o >>= 1) {
                    ull other = __shfl_down_sync(0xffffffffu, sc, o);
                    fadd2(sc, other);
                }
                if ((t & 31) == 0) sp4u[t >> 5] = sc;
                asm volatile("bar.sync 2, 64;" ::: "memory");
                if (t < 2) {
                    ull tot = sp4u[0];
                    fadd2(tot, sp4u[1]);
                    float2 v = unpk(tot);
                    float val = t ? v.y : v.x;
                    float prob = sigm(val + bs2v);
                    int m = i * (NN - 1) - (i * (i - 1)) / 2 + (j - i - 1);
                    int b = b0 + 2 * q + t;
                    float uu = uin[b * TT + m];
                    float pc = fminf(fmaxf(prob, EPSF), 1.f - EPSF);
                    float e;
                    if (pc < 0.499f || pc > 0.501f) {
                        e = (log1pf(-pc + uu * (2.f * pc - 1.f)) - log1pf(-pc))
                          / (logf(pc) - log1pf(-pc));
                    } else {
                        e = uu;
                    }
                    int rr = g_rd[m], cc = g_cd[m];
                    float* adj = out + OUT_ADJ + b * (NN * NN);
                    adj[rr * NN + cc] = e;
                    adj[cc * NN + rr] = e;
                }
            }
            pb ^= 1;
        }

        // ---- graph GRU (one pass; octants 0-3 = Wgi, 4-7 = Wgh) ----
        if (i < NN - 2) {
            const float* hfin = hBuf[pb];
            const float* ghR = gBuf[gpb];
            float* ghW = gBuf[gpb ^ 1];

            {
                ull acc[16];
                #pragma unroll
                for (int x = 0; x < 16; x++) acc[x] = 0ull;
                if (oct < 4)
                    gemm_glob<KQG>(WgiG + oct * KQG * 256 + col * 4,
                                   hfin + oct * KQG * 8, acc);
                else
                    gemm_glob<KQG>(WghG + (oct - 4) * KQG * 256 + col * 4,
                                   ghR + (oct - 4) * KQG * 8, acc);
                #pragma unroll
                for (int g = 0; g < 4; g++) {
                    #pragma unroll
                    for (int pp = 0; pp < 2; pp++) {
                        *(ulonglong2*)(sred + ((oct * 8 + g * 2 + pp) * 256 + col * 4)) =
                            make_ulonglong2(acc[g * 4 + 2 * pp], acc[g * 4 + 2 * pp + 1]);
                    }
                }
            }
            __syncthreads();

            if (t < 128) {
                float vi[3][4], vh[3][4];
                #pragma unroll
                for (int g = 0; g < 3; g++) {
                    ull i0 = 0ull, i1 = 0ull, h0 = 0ull, h1 = 0ull;
                    #pragma unroll
                    for (int o = 0; o < 4; o++) {
                        ulonglong2 v = *(const ulonglong2*)
                            (sred + ((o * 8 + g * 2 + ph) * 256 + col * 4));
                        fadd2(i0, v.x); fadd2(i1, v.y);
                    }
                    #pragma unroll
                    for (int o = 4; o < 8; o++) {
                        ulonglong2 v = *(const ulonglong2*)
                            (sred + ((o * 8 + g * 2 + ph) * 256 + col * 4));
                        fadd2(h0, v.x); fadd2(h1, v.y);
                    }
                    float2 a = unpk(i0), b = unpk(i1);
                    vi[g][0] = a.x + bgia[g]; vi[g][1] = a.y + bgia[g];
                    vi[g][2] = b.x + bgia[g]; vi[g][3] = b.y + bgia[g];
                    float2 c = unpk(h0), d = unpk(h1);
                    vh[g][0] = c.x + bgha[g]; vh[g][1] = c.y + bgha[g];
                    vh[g][2] = d.x + bgha[g]; vh[g][3] = d.y + bgha[g];
                }
                float4 go4 = *(const float4*)(ghR + hc * 8 + ph * 4);
                float go[4] = { go4.x, go4.y, go4.z, go4.w };
                float hn[4];
                #pragma unroll
                for (int r = 0; r < 4; r++) {
                    float rr = sigm(vi[0][r] + vh[0][r]);
                    float zz = sigm(vi[1][r] + vh[1][r]);
                    float nn = ftanh(vi[2][r] + rr * vh[2][r]);
                    hn[r] = (1.f - zz) * nn + zz * go[r];
                }
                ull lo = pk(hn[0], hn[1]);
                ull hi = pk(hn[2], hn[3]);
                float* dp = ghW + hc * 8 + ph * 4;
                ((ull*)dp)[0] = lo; ((ull*)dp)[1] = hi;
                #pragma unroll
                for (int pr = 0; pr < 4; pr++) {
                    if (pr != q) {
                        st_peer64(dp, (unsigned)pr, lo);
                        st_peer64(dp + 2, (unsigned)pr, hi);
                    }
                }
            }
            EXCHANGE();
            gpb ^= 1;
        }
    }
    CLUSTER_SYNC();   // no CTA exits while peers' DSMEM stores may be in flight
}

// ==================== launch ====================
extern "C" void kernel_launch(void* const* d_in, const int* in_sizes, int n_in,
                              void* d_out, int out_size)
{
    const float* z     = (const float*)d_in[0];
    const float* nf    = (const float*)d_in[1];
    const float* u     = (const float*)d_in[2];
    const float* Wih_n = (const float*)d_in[3];
    const float* Whh_n = (const float*)d_in[4];
    const float* bih_n = (const float*)d_in[5];
    const float* bhh_n = (const float*)d_in[6];
    const float* Wih_g = (const float*)d_in[7];
    const float* Whh_g = (const float*)d_in[8];
    const float* bih_g = (const float*)d_in[9];
    const float* bhh_g = (const float*)d_in[10];
    const float* Ws1   = (const float*)d_in[11];
    const float* bs1   = (const float*)d_in[12];
    const float* Ws2   = (const float*)d_in[13];
    const float* bs2   = (const float*)d_in[14];
    float* out = (float*)d_out;

    const long total = 262144L * 3 + 1024 * 3 + 7168 * 2 + 16384
                     + BB * NN + TT + BB * NN * FF + BB * NN * NN + BB * NN;
    int blocks = (int)((total + 255) / 256);
    prep_kernel<<<blocks, 256>>>(nf, Wih_n, Whh_n, bih_n, bhh_n,
                                 Wih_g, Whh_g, bih_g, bhh_g, Ws1, out);

    cudaFuncSetAttribute(chain_kernel,
                         cudaFuncAttributeMaxDynamicSharedMemorySize, SMEM_BYTES);
    chain_kernel<<<NCTA, NT, SMEM_BYTES>>>(z, u, bs1, Ws2, bs2, out);
}

// round 14
// speedup vs baseline: 1.5813x; 1.0389x over previous
#include <cuda_runtime.h>
#include <math.h>

// ---------------- problem constants ----------------
#define BB 256
#define NN 32
#define HH 256
#define FF 7
#define TT 496
#define RR 8                 // batch rows per 4-CTA cluster
#define NCLUST (BB / RR)
#define NCTA (NCLUST * 4)    // 128 CTAs
#define NT 512
#define HPAD 260             // floats per 32-k block of h (256 + 4 pad)
#define HBUF (8 * HPAD)      // 2080 floats per h buffer
#define EPSF 1.1920929e-07f

typedef unsigned long long ull;

// ---------------- device scratch ----------------
// node weights: [q][kp(32)][col(64)][oct(8)][gate(4)]  (k = oct*32 + kp)
__device__ float g_WcN[4 * 32 * 64 * 8 * 4];
// graph weights combined: [q][kp(64)][col(64)][oct(8)][gate(4)]
//   oct: m = oct>>2 (0=Wih_g, 1=Whh_g), kq = oct&3, k = kq*64 + kp; gate3 = 0
__device__ float g_Wg2[4 * 64 * 64 * 8 * 4];
__device__ float g_bv4[4 * 256];         // node combined bias [q][col*4+g]
__device__ float g_bgi4[4 * 256];
__device__ float g_bgh4[4 * 256];
__device__ float g_PQi4[4 * FF * 256];   // one-hot gathers [q][f][col*4+g], g3=0
__device__ float g_PQj4[4 * FF * 256];
__device__ float g_Ws1T[HH * 64];        // Ws1 transposed [k][u]
__device__ int   g_idx[BB * NN];
__device__ int   g_rd[TT];
__device__ int   g_cd[TT];

// output layout (float32): [x 57344][adj 262144][batch 8192]
#define OUT_X 0
#define OUT_ADJ 57344
#define OUT_BATCH 319488

// ==================== prep kernel ====================
__global__ void prep_kernel(
    const float* __restrict__ nf,
    const float* __restrict__ Wih_n, const float* __restrict__ Whh_n,
    const float* __restrict__ bih_n, const float* __restrict__ bhh_n,
    const float* __restrict__ Wih_g, const float* __restrict__ Whh_g,
    const float* __restrict__ bih_g, const float* __restrict__ bhh_g,
    const float* __restrict__ Ws1,
    float* __restrict__ out)
{
    long t = (long)blockIdx.x * blockDim.x + threadIdx.x;

    if (t < 262144) {   // g_WcN [q][kp][col][oct][g]
        int q = (int)(t >> 16), rem = (int)(t & 65535);
        int kp = rem >> 11, r2 = rem & 2047;
        int col = r2 >> 5, oct = (r2 >> 2) & 7, g = r2 & 3;
        int k = oct * 32 + kp, hc = q * 64 + col;
        float v;
        if (g == 0)      v = Wih_n[hc * 270 + 14 + k] + Whh_n[hc * 256 + k];
        else if (g == 1) v = Wih_n[(256 + hc) * 270 + 14 + k] + Whh_n[(256 + hc) * 256 + k];
        else if (g == 2) v = Wih_n[(512 + hc) * 270 + 14 + k];
        else             v = Whh_n[(512 + hc) * 256 + k];
        g_WcN[t] = v; return;
    }
    t -= 262144;
    if (t < 524288) {   // g_Wg2 [q][kp][col][oct][g]
        int q = (int)(t >> 17), rem = (int)(t & 131071);
        int kp = rem >> 11, r2 = rem & 2047;
        int col = r2 >> 5, oct = (r2 >> 2) & 7, g = r2 & 3;
        int m = oct >> 2, kq = oct & 3;
        int k = kq * 64 + kp, hc = q * 64 + col;
        float v = 0.f;
        if (g < 3) v = m ? Whh_g[(g * 256 + hc) * 256 + k]
                         : Wih_g[(g * 256 + hc) * 256 + k];
        g_Wg2[t] = v; return;
    }
    t -= 524288;
    if (t < 1024) {     // g_bv4
        int q = (int)(t >> 8), lc = (int)(t & 255);
        int g = lc & 3, col = lc >> 2, hc = q * 64 + col;
        float v;
        if (g == 0)      v = bih_n[hc] + bhh_n[hc];
        else if (g == 1) v = bih_n[256 + hc] + bhh_n[256 + hc];
        else if (g == 2) v = bih_n[512 + hc];
        else             v = bhh_n[512 + hc];
        g_bv4[t] = v; return;
    }
    t -= 1024;
    if (t < 1024) {     // g_bgi4
        int q = (int)(t >> 8), lc = (int)(t & 255);
        int g = lc & 3, col = lc >> 2, hc = q * 64 + col;
        g_bgi4[t] = (g < 3) ? bih_g[g * 256 + hc] : 0.f; return;
    }
    t -= 1024;
    if (t < 1024) {     // g_bgh4
        int q = (int)(t >> 8), lc = (int)(t & 255);
        int g = lc & 3, col = lc >> 2, hc = q * 64 + col;
        g_bgh4[t] = (g < 3) ? bhh_g[g * 256 + hc] : 0.f; return;
    }
    t -= 1024;
    if (t < 7168) {     // g_PQi4
        int q = (int)(t / 1792), rem = (int)(t % 1792);
        int f = rem >> 8, lc = rem & 255;
        int g = lc & 3, col = lc >> 2, hc = q * 64 + col;
        g_PQi4[t] = (g < 3) ? Wih_n[(g * 256 + hc) * 270 + f] : 0.f; return;
    }
    t -= 7168;
    if (t < 7168) {     // g_PQj4
        int q = (int)(t / 1792), rem = (int)(t % 1792);
        int f = rem >> 8, lc = rem & 255;
        int g = lc & 3, col = lc >> 2, hc = q * 64 + col;
        g_PQj4[t] = (g < 3) ? Wih_n[(g * 256 + hc) * 270 + 7 + f] : 0.f; return;
    }
    t -= 7168;
    if (t < 16384) {    // W1T [k][u]
        int k = (int)(t >> 6), u = (int)(t & 63);
        g_Ws1T[t] = Ws1[u * 256 + k]; return;
    }
    t -= 16384;
    if (t < BB * NN) {  // argmax one-hot
        const float* p = nf + t * FF;
        int best = 0;
        #pragma unroll
        for (int f = 0; f < FF; f++) if (p[f] > 0.5f) best = f;
        g_idx[t] = best; return;
    }
    t -= BB * NN;
    if (t < TT) {       // anti-diagonal placement
        int m = (int)t;
        int d = (int)((1.0 + sqrt(1.0 + 8.0 * (double)m)) * 0.5);
        while (d * (d - 1) / 2 > m) d--;
        while ((d + 1) * d / 2 <= m) d++;
        int rr = m - d * (d - 1) / 2;
        g_rd[m] = rr; g_cd[m] = rr + NN - d; return;
    }
    t -= TT;
    if (t < BB * NN * FF) { out[OUT_X + t] = nf[t]; return; }
    t -= BB * NN * FF;
    if (t < BB * NN * NN) { out[OUT_ADJ + t] = 0.f; return; }
    t -= BB * NN * NN;
    if (t < BB * NN) { out[OUT_BATCH + t] = (float)(t >> 5); return; }
}

// ==================== helpers ====================
__device__ __forceinline__ float fex2(float x) {
    float r; asm("ex2.approx.ftz.f32 %0, %1;" : "=f"(r) : "f"(x)); return r;
}
__device__ __forceinline__ float frcp(float x) {
    float r; asm("rcp.approx.ftz.f32 %0, %1;" : "=f"(r) : "f"(x)); return r;
}
__device__ __forceinline__ float sigm(float x) {
    return frcp(1.f + fex2(-1.4426950408889634f * x));
}
__device__ __forceinline__ float ftanh(float x) {
    return 1.f - 2.f * frcp(1.f + fex2(2.8853900817779268f * x));
}
__device__ __forceinline__ void ffma2(ull& d, ull a, ull b) {
    asm("fma.rn.f32x2 %0, %1, %2, %0;" : "+l"(d) : "l"(a), "l"(b));
}
__device__ __forceinline__ void fadd2(ull& d, ull a) {
    asm("add.rn.f32x2 %0, %0, %1;" : "+l"(d) : "l"(a));
}
__device__ __forceinline__ ull dup2(float w) {
    ull r;
    asm("mov.b64 %0, {%1, %1};" : "=l"(r) : "r"(__float_as_uint(w)));
    return r;
}
__device__ __forceinline__ float2 unpk(ull v) {
    float2 r;
    r.x = __uint_as_float((unsigned)(v & 0xffffffffu));
    r.y = __uint_as_float((unsigned)(v >> 32));
    return r;
}
__device__ __forceinline__ ull pk(float x, float y) {
    return ((ull)__float_as_uint(y) << 32) | (ull)__float_as_uint(x);
}
__device__ __forceinline__ void st_peer64(float* p, unsigned peer, ull bits) {
    unsigned la = (unsigned)__cvta_generic_to_shared(p);
    unsigned ra;
    asm volatile("mapa.shared::cluster.u32 %0, %1, %2;" : "=r"(ra) : "r"(la), "r"(peer));
    asm volatile("st.shared::cluster.b64 [%0], %1;" :: "r"(ra), "l"(bits) : "memory");
}
__device__ __forceinline__ void st_peer64a(unsigned laddr, unsigned peer, ull bits) {
    unsigned ra;
    asm volatile("mapa.shared::cluster.u32 %0, %1, %2;" : "=r"(ra) : "r"(laddr), "r"(peer));
    asm volatile("st.shared::cluster.b64 [%0], %1;" :: "r"(ra), "l"(bits) : "memory");
}
__device__ __forceinline__ void mbar_init(unsigned addr, unsigned cnt) {
    asm volatile("mbarrier.init.shared.b64 [%0], %1;" :: "r"(addr), "r"(cnt) : "memory");
}
__device__ __forceinline__ void mbar_arrive_cluster(unsigned laddr, unsigned rank) {
    unsigned ra;
    asm volatile("mapa.shared::cluster.u32 %0, %1, %2;" : "=r"(ra) : "r"(laddr), "r"(rank));
    asm volatile("mbarrier.arrive.release.cluster.shared::cluster.b64 _, [%0];"
                 :: "r"(ra) : "memory");
}
__device__ __forceinline__ void mbar_wait(unsigned addr, unsigned parity) {
    asm volatile(
        "{\n\t.reg .pred P1;\n\t"
        "WAIT_LOOP_%=:\n\t"
        "mbarrier.try_wait.parity.acquire.cluster.shared::cta.b64 P1, [%0], %1, 0x989680;\n\t"
        "@P1 bra.uni WAIT_DONE_%=;\n\t"
        "bra.uni WAIT_LOOP_%=;\n\t"
        "WAIT_DONE_%=:\n\t}"
        :: "r"(addr), "r"(parity) : "memory");
}
#define CLUSTER_SYNC() do { \
    asm volatile("barrier.cluster.arrive.aligned;" ::: "memory"); \
    asm volatile("barrier.cluster.wait.aligned;" ::: "memory"); } while (0)

#define EXCHANGE() do { \
    __syncthreads(); \
    unsigned mb_ = mbarB32 + (unsigned)((xstep & 1) * 8); \
    if (t < 4) mbar_arrive_cluster(mb_, (unsigned)t); \
    mbar_wait(mb_, (unsigned)((xstep >> 1) & 1)); \
    xstep++; \
} while (0)

// ---- gemm core: thread owns 4 gates of one col, one K-octant ----
// acc[g*4 + p] = f32x2 over rows (2p, 2p+1)
__device__ __forceinline__ void gbody(const float4 w, const float* __restrict__ hk,
                                      ull acc[16])
{
    ulonglong2 h01 = *(const ulonglong2*)(hk);
    ulonglong2 h23 = *(const ulonglong2*)(hk + 4);
    ull wd;
    wd = dup2(w.x);
    ffma2(acc[0], wd, h01.x); ffma2(acc[1], wd, h01.y);
    ffma2(acc[2], wd, h23.x); ffma2(acc[3], wd, h23.y);
    wd = dup2(w.y);
    ffma2(acc[4], wd, h01.x); ffma2(acc[5], wd, h01.y);
    ffma2(acc[6], wd, h23.x); ffma2(acc[7], wd, h23.y);
    wd = dup2(w.z);
    ffma2(acc[8],  wd, h01.x); ffma2(acc[9],  wd, h01.y);
    ffma2(acc[10], wd, h23.x); ffma2(acc[11], wd, h23.y);
    wd = dup2(w.w);
    ffma2(acc[12], wd, h01.x); ffma2(acc[13], wd, h01.y);
    ffma2(acc[14], wd, h23.x); ffma2(acc[15], wd, h23.y);
}

// ---------------- smem layout (float offsets) ----------------
#define SO_W1L  0                           // 4096 (W1T local slice [c][u])
#define SO_HA   4096
#define SO_HB   (SO_HA + HBUF)              // 6176
#define SO_GA   (SO_HB + HBUF + 4)          // 8260  (+4: bank-shift vs hBuf)
#define SO_GB   (SO_GA + HBUF)              // 10340
#define SO_PQI  (SO_GB + HBUF)              // 12420
#define SO_PQJ  (SO_PQI + 1792)             // 14212
#define SO_PB   (SO_PQJ + 1792)             // 16004  score partials 2par x 8src x 64 ull
#define SO_SP4  (SO_PB + 2048)              // 18052  2 ull
#define SO_IDX  (SO_SP4 + 4)                // 18056  256 ints
#define SO_MBAR (SO_IDX + 256)              // 18312  2 mbarriers
#define SMEM_FLOATS (SO_MBAR + 4)           // 18316
#define SMEM_BYTES (SMEM_FLOATS * 4)        // 73264

// ==================== main chain kernel ====================
__global__ void __launch_bounds__(NT, 1) __cluster_dims__(4, 1, 1)
chain_kernel(const float* __restrict__ z, const float* __restrict__ uin,
             const float* __restrict__ bs1, const float* __restrict__ Ws2,
             const float* __restrict__ bs2, float* __restrict__ out)
{
    extern __shared__ float sm[];
    float* sW1L = sm + SO_W1L;
    float* hBuf[2] = { sm + SO_HA, sm + SO_HB };
    float* gBuf[2] = { sm + SO_GA, sm + SO_GB };
    float* sPQi = sm + SO_PQI;
    float* sPQj = sm + SO_PQJ;
    float* sPB  = sm + SO_PB;
    ull*   sp4u = (ull*)(sm + SO_SP4);
    int*   sidx = (int*)(sm + SO_IDX);

    const int t = threadIdx.x;
    const int q = blockIdx.x & 3;
    const int cid = blockIdx.x >> 2;
    const int b0 = cid * RR;
    const unsigned sb32 = (unsigned)__cvta_generic_to_shared(sm);
    const unsigned mbarB32 = sb32 + SO_MBAR * 4;

    const float* WcG = g_WcN + q * 65536;
    const float* WgG = g_Wg2 + q * 131072;

    // ---- init smem ----
    for (int x = t; x < 4096; x += NT) sW1L[x] = g_Ws1T[q * 4096 + x];
    for (int x = t; x < FF * 256; x += NT) {
        sPQi[x] = g_PQi4[q * FF * 256 + x];
        sPQj[x] = g_PQj4[q * FF * 256 + x];
    }
    for (int x = t; x < 2048; x += NT) {      // graph h init (padded layout)
        int k = x >> 3, r = x & 7;
        gBuf[0][(k >> 5) * HPAD + (k & 31) * 8 + r] = z[(b0 + r) * HH + k];
    }
    if (t < 256) sidx[t] = g_idx[b0 * NN + t];
    if (t == 0) {
        mbar_init(mbarB32, 4);
        mbar_init(mbarB32 + 8, 4);
    }

    // roles
    const int col = t >> 3;            // 0..63
    const int oct = t & 7;             // K-octant / final row
    const bool b2 = (oct & 4) != 0;
    const bool b1 = (oct & 2) != 0;
    const bool b0v = (oct & 1) != 0;
    const int hco = (q * 2 + (col >> 5)) * HPAD + (col & 31) * 8;  // h col base
    // score roles
    const int su = t & 63;
    const int rp = (t >> 6) & 3;
    const int chalf = t >> 8;
    const float b1r  = bs1[t & 63];
    const float w2r  = Ws2[t & 63];
    const float bs2v = *bs2;

    // per-thread bias registers (col-based, all threads)
    float4 bv4  = *(const float4*)(g_bv4  + q * 256 + col * 4);
    float4 bgi4 = *(const float4*)(g_bgi4 + q * 256 + col * 4);
    float4 bgh4 = *(const float4*)(g_bgh4 + q * 256 + col * 4);
    const float bva[4]  = { bv4.x, bv4.y, bv4.z, bv4.w };
    const float bgia[3] = { bgi4.x, bgi4.y, bgi4.z };
    const float bgha[3] = { bgh4.x, bgh4.y, bgh4.z };

    __syncthreads();
    CLUSTER_SYNC();      // mbarrier inits + smem visible cluster-wide

    int pb = 0, gpb = 0;
    int xstep = 0;

    const float* WpN = WcG + col * 32 + oct * 4;     // node weight column base

    for (int i = 0; i < NN - 1; i++) {
        pb = 0;
        {   // node_h := graph_h (full padded copy)
            const float* gs = gBuf[gpb];
            float* d = hBuf[0];
            for (int x = t; x < HBUF; x += NT) d[x] = gs[x];
        }
        __syncthreads();

        const int fiT = sidx[oct * NN + i];

        for (int j = i + 1; j < NN; j++) {
            float* hR = hBuf[pb];
            float* hW = hBuf[pb ^ 1];
            const int pbsel = xstep & 1;

            // ---- node gemm: 32 k of octant oct, 8-deep prefetch ----
            ull acc[16];
            #pragma unroll
            for (int x = 0; x < 16; x++) acc[x] = 0ull;
            {
                const float* hq = hR + oct * HPAD;
                float4 wb[8];
                #pragma unroll
                for (int x = 0; x < 8; x++) wb[x] = *(const float4*)(WpN + x * 2048);
                #pragma unroll
                for (int blk = 0; blk < 4; blk++) {
                    float4 wc[8];
                    #pragma unroll
                    for (int x = 0; x < 8; x++) wc[x] = wb[x];
                    if (blk + 1 < 4) {
                        const float* np = WpN + (blk + 1) * 8 * 2048;
                        #pragma unroll
                        for (int x = 0; x < 8; x++) wb[x] = *(const float4*)(np + x * 2048);
                    }
                    const float* hkb = hq + blk * 64;
                    #pragma unroll
                    for (int x = 0; x < 8; x++) gbody(wc[x], hkb + x * 8, acc);
                }
            }

            // ---- butterfly reduce-scatter over octants (rows split each round) ----
            ull k8[8];
            #pragma unroll
            for (int g = 0; g < 4; g++) {
                #pragma unroll
                for (int pkx = 0; pkx < 2; pkx++) {
                    ull keep = b2 ? acc[g * 4 + 2 + pkx] : acc[g * 4 + pkx];
                    ull send = b2 ? acc[g * 4 + pkx]     : acc[g * 4 + 2 + pkx];
                    ull r = __shfl_xor_sync(0xffffffffu, send, 4);
                    fadd2(keep, r);
                    k8[g * 2 + pkx] = keep;
                }
            }
            ull k4[4];
            #pragma unroll
            for (int g = 0; g < 4; g++) {
                ull keep = b1 ? k8[g * 2 + 1] : k8[g * 2];
                ull send = b1 ? k8[g * 2]     : k8[g * 2 + 1];
                ull r = __shfl_xor_sync(0xffffffffu, send, 2);
                fadd2(keep, r);
                k4[g] = keep;
            }
            #pragma unroll
            for (int g = 0; g < 4; g++) {
                ull r = __shfl_xor_sync(0xffffffffu, k4[g], 1);
                fadd2(k4[g], r);
            }

            // ---- in-register GRU activation (row = oct) ----
            {
                float vg[4];
                #pragma unroll
                for (int g = 0; g < 4; g++) {
                    float2 f = unpk(k4[g]);
                    vg[g] = (b0v ? f.y : f.x) + bva[g];
                }
                const int fj = sidx[oct * NN + j];
                float4 pi = *(const float4*)(sPQi + fiT * 256 + col * 4);
                float4 pj = *(const float4*)(sPQj + fj * 256 + col * 4);
                vg[0] += pi.x + pj.x;
                vg[1] += pi.y + pj.y;
                vg[2] += pi.z + pj.z;
                float ho = hR[hco + oct];
                float gr = sigm(vg[0]);
                float gz = sigm(vg[1]);
                float gn = ftanh(vg[2] + gr * vg[3]);
                float hn = (1.f - gz) * gn + gz * ho;
                float hpeer = __shfl_xor_sync(0xffffffffu, hn, 1);
                if (!b0v) {
                    ull bits = pk(hn, hpeer);
                    float* dp = hW + hco + oct;
                    *(ull*)dp = bits;
                    #pragma unroll
                    for (int pr = 0; pr < 4; pr++)
                        if (pr != q) st_peer64(dp, (unsigned)pr, bits);
                }
            }
            __syncthreads();   // local h slice complete

            // ---- packed score partials over own 64 cols (ride exchange) ----
            {
                ull sacc = 0ull;
                const float* wp = sW1L + chalf * 32 * 64 + su;
                const float* hp = hW + (q * 2 + chalf) * HPAD + 2 * rp;
                #pragma unroll 8
                for (int c = 0; c < 32; c++)
                    ffma2(sacc, dup2(wp[c * 64]), *(const ull*)(hp + c * 8));
                unsigned laddr = sb32 +
                    (unsigned)((SO_PB + pbsel * 1024 + chalf * 512 + q * 128 + su * 2) * 4);
                st_peer64a(laddr, (unsigned)rp, sacc);
            }
            EXCHANGE();

            // ---- finalize score + edge for own rows 2q, 2q+1 (t < 64) ----
            if (t < 64) {
                ull sum = 0ull;
                const ull* pbp = (const ull*)(sPB + pbsel * 1024);
                #pragma unroll
                for (int x = 0; x < 8; x++) fadd2(sum, pbp[x * 64 + t]);
                float2 s = unpk(sum);
                float hx = fmaxf(s.x + b1r, 0.f) * w2r;
                float hy = fmaxf(s.y + b1r, 0.f) * w2r;
                ull sc = pk(hx, hy);
                #pragma unroll
                for (int o = 16; o; o >>= 1) {
                    ull other = __shfl_down_sync(0xffffffffu, sc, o);
                    fadd2(sc, other);
                }
                if ((t & 31) == 0) sp4u[t >> 5] = sc;
                asm volatile("bar.sync 2, 64;" ::: "memory");
                if (t < 2) {
                    ull tot = sp4u[0];
                    fadd2(tot, sp4u[1]);
                    float2 v = unpk(tot);
                    float val = t ? v.y : v.x;
                    float prob = sigm(val + bs2v);
                    int m = i * (NN - 1) - (i * (i - 1)) / 2 + (j - i - 1);
                    int b = b0 + 2 * q + t;
                    float uu = uin[b * TT + m];
                    float pc = fminf(fmaxf(prob, EPSF), 1.f - EPSF);
                    float e;
                    if (pc < 0.499f || pc > 0.501f) {
                        e = (log1pf(-pc + uu * (2.f * pc - 1.f)) - log1pf(-pc))
                          / (logf(pc) - log1pf(-pc));
                    } else {
                        e = uu;
                    }
                    int rr = g_rd[m], cc = g_cd[m];
                    float* adj = out + OUT_ADJ + b * (NN * NN);
                    adj[rr * NN + cc] = e;
                    adj[cc * NN + rr] = e;
                }
            }
            pb ^= 1;
        }

        // ---- graph GRU: octs 0-3 = Wgi quarters, 4-7 = Wgh quarters ----
        if (i < NN - 2) {
            const float* hfin = hBuf[pb];
            const float* ghR = gBuf[gpb];
            float* ghW = gBuf[gpb ^ 1];

            ull acc[16];
            #pragma unroll
            for (int x = 0; x < 16; x++) acc[x] = 0ull;
            {
                const float* hgb = (b2 ? ghR : hfin) + (oct & 3) * (2 * HPAD);
                const float* Wp = WgG + col * 32 + oct * 4;
                float4 wb[8];
                #pragma unroll
                for (int x = 0; x < 8; x++) wb[x] = *(const float4*)(Wp + x * 2048);
                #pragma unroll
                for (int blk = 0; blk < 8; blk++) {
                    float4 wc[8];
                    #pragma unroll
                    for (int x = 0; x < 8; x++) wc[x] = wb[x];
                    if (blk + 1 < 8) {
                        const float* np = Wp + (blk + 1) * 8 * 2048;
                        #pragma unroll
                        for (int x = 0; x < 8; x++) wb[x] = *(const float4*)(np + x * 2048);
                    }
                    const float* hkb = hgb + ((blk & 4) ? (HPAD - 256) : 0) + blk * 64;
                    #pragma unroll
                    for (int x = 0; x < 8; x++) gbody(wc[x], hkb + x * 8, acc);
                }
            }

            // butterfly: xor2 (row-half by b1), xor1 (row-pair by b0), xor4 (vi<->vh)
            ull k8g[8];
            #pragma unroll
            for (int g = 0; g < 4; g++) {
                #pragma unroll
                for (int pkx = 0; pkx < 2; pkx++) {
                    ull keep = b1 ? acc[g * 4 + 2 + pkx] : acc[g * 4 + pkx];
                    ull send = b1 ? acc[g * 4 + pkx]     : acc[g * 4 + 2 + pkx];
                    ull r = __shfl_xor_sync(0xffffffffu, send, 2);
                    fadd2(keep, r);
                    k8g[g * 2 + pkx] = keep;
                }
            }
            ull k4g[4];
            #pragma unroll
            for (int g = 0; g < 4; g++) {
                ull keep = b0v ? k8g[g * 2 + 1] : k8g[g * 2];
                ull send = b0v ? k8g[g * 2]     : k8g[g * 2 + 1];
                ull r = __shfl_xor_sync(0xffffffffu, send, 1);
                fadd2(keep, r);
                k4g[g] = keep;
            }
            {
                const int row = (b1 ? 4 : 0) + (b0v ? 2 : 0) + (b2 ? 1 : 0);
                float vi[3], vh[3];
                #pragma unroll
                for (int g = 0; g < 3; g++) {
                    ull other = __shfl_xor_sync(0xffffffffu, k4g[g], 4);
                    ull iu = b2 ? other : k4g[g];
                    ull hu = b2 ? k4g[g] : other;
                    float2 fi_ = unpk(iu), fh_ = unpk(hu);
                    vi[g] = (b2 ? fi_.y : fi_.x) + bgia[g];
                    vh[g] = (b2 ? fh_.y : fh_.x) + bgha[g];
                }
                float go = ghR[hco + row];
                float rr = sigm(vi[0] + vh[0]);
                float zz = sigm(vi[1] + vh[1]);
                float nn = ftanh(vi[2] + rr * vh[2]);
                float hn = (1.f - zz) * nn + zz * go;
                float hpeer = __shfl_xor_sync(0xffffffffu, hn, 4);
                if (!b2) {   // row even
                    ull bits = pk(hn, hpeer);
                    float* dp = ghW + hco + row;
                    *(ull*)dp = bits;
                    #pragma unroll
                    for (int pr = 0; pr < 4; pr++)
                        if (pr != q) st_peer64(dp, (unsigned)pr, bits);
                }
            }
            EXCHANGE();
            gpb ^= 1;
        }
    }
    CLUSTER_SYNC();
}

// ==================== launch ====================
extern "C" void kernel_launch(void* const* d_in, const int* in_sizes, int n_in,
                              void* d_out, int out_size)
{
    const float* z     = (const float*)d_in[0];
    const float* nf    = (const float*)d_in[1];
    const float* u     = (const float*)d_in[2];
    const float* Wih_n = (const float*)d_in[3];
    const float* Whh_n = (const float*)d_in[4];
    const float* bih_n = (const float*)d_in[5];
    const float* bhh_n = (const float*)d_in[6];
    const float* Wih_g = (const float*)d_in[7];
    const float* Whh_g = (const float*)d_in[8];
    const float* bih_g = (const float*)d_in[9];
    const float* bhh_g = (const float*)d_in[10];
    const float* Ws1   = (const float*)d_in[11];
    const float* bs1   = (const float*)d_in[12];
    const float* Ws2   = (const float*)d_in[13];
    const float* bs2   = (const float*)d_in[14];
    float* out = (float*)d_out;

    const long total = 262144L + 524288L + 1024 * 3 + 7168 * 2 + 16384
                     + BB * NN + TT + BB * NN * FF + BB * NN * NN + BB * NN;
    int blocks = (int)((total + 255) / 256);
    prep_kernel<<<blocks, 256>>>(nf, Wih_n, Whh_n, bih_n, bhh_n,
                                 Wih_g, Whh_g, bih_g, bhh_g, Ws1, out);

    cudaFuncSetAttribute(chain_kernel,
                         cudaFuncAttributeMaxDynamicSharedMemorySize, SMEM_BYTES);
    chain_kernel<<<NCTA, NT, SMEM_BYTES>>>(z, u, bs1, Ws2, bs2, out);
}